// round 2
// baseline (speedup 1.0000x reference)
#include <cuda_runtime.h>

#define NMAX 2000128
#define GRID_MAX 34000000
#define CPB 8192

__device__ int4 g_cellv[GRID_MAX / 4];
__device__ int g_merge[NMAX];
__device__ ushort4 g_vc[NMAX];
__device__ unsigned g_keyA[NMAX];
__device__ unsigned g_keyB[NMAX];
__device__ int g_vcount[NMAX];
__device__ int g_voffset[NMAX];
__device__ int g_cellof[NMAX];
__device__ int g_bsums[8448];
__device__ unsigned g_hist[256 * 512];
__device__ unsigned g_binbase[256];

struct Stats {
    unsigned pcmin_bits[4];
    unsigned hmin_e, hmax_e;
    int vcmin[4], vcmax[4];
    int dims[4];
    int total;
    float hmin, hmax;
};
__device__ Stats g_st;

__device__ __forceinline__ unsigned fenc(float f) {
    unsigned b = __float_as_uint(f);
    return (b & 0x80000000u) ? ~b : (b | 0x80000000u);
}
__device__ __forceinline__ float fdec(unsigned u) {
    return __uint_as_float((u & 0x80000000u) ? (u ^ 0x80000000u) : ~u);
}

__global__ void k_init() {
    int t = threadIdx.x;
    if (t < 4) {
        g_st.pcmin_bits[t] = 0x7F800000u;
        g_st.vcmin[t] = 0x7FFFFFFF;
        g_st.vcmax[t] = (int)0x80000000;
    }
    if (t == 4) { g_st.hmin_e = 0xFFFFFFFFu; g_st.hmax_e = 0u; }
}

__global__ void k_zero_cells() {
    long long i = (long long)blockIdx.x * blockDim.x + threadIdx.x;
    long long st = (long long)gridDim.x * blockDim.x;
    for (; i < GRID_MAX / 4; i += st) g_cellv[i] = make_int4(0, 0, 0, 0);
}

__global__ void k_zero_out(float* p, long long n) {
    long long i = (long long)blockIdx.x * blockDim.x + threadIdx.x;
    long long st = (long long)gridDim.x * blockDim.x;
    for (; i < n; i += st) p[i] = 0.0f;
}

__global__ void k_stats(const float4* bxyz, const float* h, int n) {
    float m0 = 3.4e38f, m1 = 3.4e38f, m2 = 3.4e38f, m3 = 3.4e38f;
    unsigned he0 = 0xFFFFFFFFu, he1 = 0u;
    for (int i = blockIdx.x * blockDim.x + threadIdx.x; i < n; i += gridDim.x * blockDim.x) {
        float4 p = bxyz[i];
        m0 = fminf(m0, p.x); m1 = fminf(m1, p.y);
        m2 = fminf(m2, p.z); m3 = fminf(m3, p.w);
        unsigned e = fenc(h[i]);
        he0 = min(he0, e); he1 = max(he1, e);
    }
    #pragma unroll
    for (int o = 16; o; o >>= 1) {
        m0 = fminf(m0, __shfl_down_sync(~0u, m0, o));
        m1 = fminf(m1, __shfl_down_sync(~0u, m1, o));
        m2 = fminf(m2, __shfl_down_sync(~0u, m2, o));
        m3 = fminf(m3, __shfl_down_sync(~0u, m3, o));
        he0 = min(he0, __shfl_down_sync(~0u, he0, o));
        he1 = max(he1, __shfl_down_sync(~0u, he1, o));
    }
    if ((threadIdx.x & 31) == 0) {
        atomicMin(&g_st.pcmin_bits[0], __float_as_uint(m0));
        atomicMin(&g_st.pcmin_bits[1], __float_as_uint(m1));
        atomicMin(&g_st.pcmin_bits[2], __float_as_uint(m2));
        atomicMin(&g_st.pcmin_bits[3], __float_as_uint(m3));
        atomicMin(&g_st.hmin_e, he0);
        atomicMax(&g_st.hmax_e, he1);
    }
}

__global__ void k_vc(const float4* bxyz, const float* vs, int n) {
    float mn0 = __uint_as_float(g_st.pcmin_bits[0]);
    float mn1 = __uint_as_float(g_st.pcmin_bits[1]);
    float mn2 = __uint_as_float(g_st.pcmin_bits[2]);
    float mn3 = __uint_as_float(g_st.pcmin_bits[3]);
    float v0 = vs[0], v1 = vs[1], v2 = vs[2], v3 = vs[3];
    int a0 = 0x7FFFFFFF, a1 = a0, a2 = a0, a3 = a0;
    int b0 = (int)0x80000000, b1 = b0, b2 = b0, b3 = b0;
    for (int i = blockIdx.x * blockDim.x + threadIdx.x; i < n; i += gridDim.x * blockDim.x) {
        float4 p = bxyz[i];
        int c0 = (int)floorf(__fdiv_rn(__fsub_rn(p.x, mn0), v0));
        int c1 = (int)floorf(__fdiv_rn(__fsub_rn(p.y, mn1), v1));
        int c2 = (int)floorf(__fdiv_rn(__fsub_rn(p.z, mn2), v2));
        int c3 = (int)floorf(__fdiv_rn(__fsub_rn(p.w, mn3), v3));
        g_vc[i] = make_ushort4((unsigned short)c0, (unsigned short)c1,
                               (unsigned short)c2, (unsigned short)c3);
        a0 = min(a0, c0); b0 = max(b0, c0);
        a1 = min(a1, c1); b1 = max(b1, c1);
        a2 = min(a2, c2); b2 = max(b2, c2);
        a3 = min(a3, c3); b3 = max(b3, c3);
    }
    #pragma unroll
    for (int o = 16; o; o >>= 1) {
        a0 = min(a0, __shfl_down_sync(~0u, a0, o)); b0 = max(b0, __shfl_down_sync(~0u, b0, o));
        a1 = min(a1, __shfl_down_sync(~0u, a1, o)); b1 = max(b1, __shfl_down_sync(~0u, b1, o));
        a2 = min(a2, __shfl_down_sync(~0u, a2, o)); b2 = max(b2, __shfl_down_sync(~0u, b2, o));
        a3 = min(a3, __shfl_down_sync(~0u, a3, o)); b3 = max(b3, __shfl_down_sync(~0u, b3, o));
    }
    if ((threadIdx.x & 31) == 0) {
        atomicMin(&g_st.vcmin[0], a0); atomicMax(&g_st.vcmax[0], b0);
        atomicMin(&g_st.vcmin[1], a1); atomicMax(&g_st.vcmax[1], b1);
        atomicMin(&g_st.vcmin[2], a2); atomicMax(&g_st.vcmax[2], b2);
        atomicMin(&g_st.vcmin[3], a3); atomicMax(&g_st.vcmax[3], b3);
    }
}

__global__ void k_dims() {
    int total = 1;
    for (int k = 0; k < 4; k++) {
        g_st.dims[k] = g_st.vcmax[k] - g_st.vcmin[k] + 1;
        total *= g_st.dims[k];
    }
    g_st.total = total;
    g_st.hmin = fdec(g_st.hmin_e);
    g_st.hmax = fdec(g_st.hmax_e);
}

__global__ void k_merge(float* out, long long V, int n) {
    int* cell = (int*)g_cellv;
    int d1 = g_st.dims[1], d2 = g_st.dims[2], d3 = g_st.dims[3];
    int m0 = g_st.vcmin[0], m1 = g_st.vcmin[1], m2 = g_st.vcmin[2], m3 = g_st.vcmin[3];
    long long O9 = 52LL * V + n;
    for (int i = blockIdx.x * blockDim.x + threadIdx.x; i < n; i += gridDim.x * blockDim.x) {
        ushort4 v = g_vc[i];
        int c0 = (int)v.x - m0, c1 = (int)v.y - m1, c2 = (int)v.z - m2, c3 = (int)v.w - m3;
        int m = ((c0 * d1 + c1) * d2 + c2) * d3 + c3;
        g_merge[i] = m;
        atomicAdd(&cell[m], 1);
        *(float4*)&out[O9 + 4LL * i] = make_float4((float)c0, (float)c1, (float)c2, (float)c3);
    }
}

__device__ __forceinline__ int blockScanExcl256(int v, int* shw, int& total) {
    int lane = threadIdx.x & 31, w = threadIdx.x >> 5;
    int x = v;
    #pragma unroll
    for (int o = 1; o < 32; o <<= 1) { int y = __shfl_up_sync(~0u, x, o); if (lane >= o) x += y; }
    if (lane == 31) shw[w] = x;
    __syncthreads();
    if (threadIdx.x < 8) {
        int s = shw[threadIdx.x];
        #pragma unroll
        for (int o = 1; o < 8; o <<= 1) { int y = __shfl_up_sync(0xFFu, s, o); if ((int)threadIdx.x >= o) s += y; }
        shw[threadIdx.x] = s;
    }
    __syncthreads();
    int excl = (w ? shw[w - 1] : 0) + x - v;
    total = shw[7];
    __syncthreads();
    return excl;
}

__global__ void k_scan_partial(int mode, int n_in) {
    const int* in = mode ? g_vcount : (const int*)g_cellv;
    int n = mode ? n_in : g_st.total;
    __shared__ int shw[8];
    long long base = (long long)blockIdx.x * CPB;
    int s = 0;
    for (int it = 0; it < CPB / 256; it++) {
        long long idx = base + it * 256 + threadIdx.x;
        if (idx < n) { int x = in[idx]; s += mode ? x : (x != 0); }
    }
    #pragma unroll
    for (int o = 16; o; o >>= 1) s += __shfl_down_sync(~0u, s, o);
    if ((threadIdx.x & 31) == 0) shw[threadIdx.x >> 5] = s;
    __syncthreads();
    if (threadIdx.x == 0) {
        int t = 0;
        for (int i = 0; i < 8; i++) t += shw[i];
        g_bsums[blockIdx.x] = t;
    }
}

__global__ void k_scan_bsums(int nb) {
    __shared__ int sh[32];
    int t = threadIdx.x, lane = t & 31, w = t >> 5;
    int c = (nb + 1023) / 1024;
    int loc[16];
    int s = 0;
    for (int j = 0; j < c; j++) {
        int idx = t * c + j;
        int v = (idx < nb) ? g_bsums[idx] : 0;
        loc[j] = s; s += v;
    }
    int x = s;
    #pragma unroll
    for (int o = 1; o < 32; o <<= 1) { int y = __shfl_up_sync(~0u, x, o); if (lane >= o) x += y; }
    if (lane == 31) sh[w] = x;
    __syncthreads();
    if (t < 32) {
        int v2 = sh[t];
        #pragma unroll
        for (int o = 1; o < 32; o <<= 1) { int y = __shfl_up_sync(~0u, v2, o); if (t >= o) v2 += y; }
        sh[t] = v2;
    }
    __syncthreads();
    int excl = (w ? sh[w - 1] : 0) + x - s;
    for (int j = 0; j < c; j++) {
        int idx = t * c + j;
        if (idx < nb) g_bsums[idx] = excl + loc[j];
    }
}

__global__ void k_scan_final_cells() {
    __shared__ int shw[8];
    int* cell = (int*)g_cellv;
    int n = g_st.total;
    long long start = (long long)blockIdx.x * CPB;
    if (start >= n) return;
    int base = g_bsums[blockIdx.x];
    for (int it = 0; it < CPB / 256; it++) {
        long long idx = start + it * 256 + threadIdx.x;
        int cnt = (idx < n) ? cell[idx] : 0;
        int occ = cnt > 0;
        int tot;
        int excl = blockScanExcl256(occ, shw, tot);
        if (occ) {
            int r = base + excl;
            g_vcount[r] = cnt;
            g_cellof[r] = (int)idx;
            cell[idx] = r;
        }
        base += tot;
    }
}

__global__ void k_scan_final_vox(int nV) {
    __shared__ int shw[8];
    long long start = (long long)blockIdx.x * CPB;
    if (start >= nV) return;
    int base = g_bsums[blockIdx.x];
    for (int it = 0; it < CPB / 256; it++) {
        long long idx = start + it * 256 + threadIdx.x;
        int v = (idx < nV) ? g_vcount[idx] : 0;
        int tot;
        int excl = blockScanExcl256(v, shw, tot);
        if (idx < nV) g_voffset[idx] = base + excl;
        base += tot;
    }
}

__global__ void k_accum(const float* bxyz, const float* feat, float* out, long long V, int n) {
    long long gw = ((long long)blockIdx.x * blockDim.x + threadIdx.x) >> 5;
    int lane = threadIdx.x & 31;
    if (gw >= n) return;
    int i = (int)gw;
    int r = ((const int*)g_cellv)[g_merge[i]];
    if (lane == 0) out[52LL * V + i] = (float)r;
    float f = feat[(long long)i * 32 + lane];
    atomicAdd(&out[19LL * V + (long long)r * 32 + lane], f);
    if (lane < 4) {
        float b = bxyz[(long long)i * 4 + lane];
        atomicAdd(&out[15LL * V + (long long)r * 4 + lane], b);
    }
}

__global__ void k_voxfin(float* out, const float* vs, long long V) {
    long long gw = ((long long)blockIdx.x * blockDim.x + threadIdx.x) >> 5;
    int lane = threadIdx.x & 31;
    if (gw >= V) return;
    long long r = gw;
    float fc = (float)g_vcount[r];
    long long o6 = 19LL * V + r * 32 + lane;
    out[o6] = __fdiv_rn(out[o6], fc);
    float mean = 0.0f;
    if (lane < 4) {
        long long o5 = 15LL * V + r * 4 + lane;
        mean = __fdiv_rn(out[o5], fc);
        out[o5] = mean;
    }
    float mb = __shfl_sync(~0u, mean, 0);
    float mx = __shfl_sync(~0u, mean, 1);
    float my = __shfl_sync(~0u, mean, 2);
    float mz = __shfl_sync(~0u, mean, 3);
    if (lane == 0) {
        int c = g_cellof[r];
        int d1 = g_st.dims[1], d2 = g_st.dims[2], d3 = g_st.dims[3];
        int c3 = c % d3; c /= d3;
        int c2 = c % d2; c /= d2;
        int c1 = c % d1;
        int c0 = c / d1;
        out[r] = (float)(int)rintf(mb);
        out[V + r * 3 + 0] = mx;
        out[V + r * 3 + 1] = my;
        out[V + r * 3 + 2] = mz;
        int cc[3] = {c1, c2, c3};
        #pragma unroll
        for (int k = 0; k < 3; k++) {
            float vsk = vs[k + 1];
            float mnk = __uint_as_float(g_st.pcmin_bits[k + 1]);
            float t = __fadd_rn(__fmul_rn((float)cc[k], vsk), mnk);
            float ctr = __fadd_rn(t, __fdiv_rn(vsk, 2.0f));
            out[4LL * V + r * 3 + k] = ctr;
            out[7LL * V + r * 4 + 1 + k] = ctr;
        }
        out[7LL * V + r * 4 + 0] = mb;
        out[11LL * V + r * 4 + 0] = (float)c0;
        out[11LL * V + r * 4 + 1] = (float)c1;
        out[11LL * V + r * 4 + 2] = (float)c2;
        out[11LL * V + r * 4 + 3] = (float)c3;
    }
}

__global__ void k_tval(const float* h, const float* out, int n, long long V) {
    float mn = g_st.hmin, mx = g_st.hmax;
    for (int i = blockIdx.x * blockDim.x + threadIdx.x; i < n; i += gridDim.x * blockDim.x) {
        float vf = out[52LL * V + i];
        g_keyA[i] = fenc(__fadd_rn(__fsub_rn(h[i], mn), __fmul_rn(vf, mx)));
    }
}

__global__ void k_hist(int pass, int n, int nblk) {
    __shared__ unsigned sh[256];
    const unsigned* src = (pass & 1) ? g_keyB : g_keyA;
    int shift = pass * 8;
    if (threadIdx.x < 256) sh[threadIdx.x] = 0;
    __syncthreads();
    int base = blockIdx.x * 4096;
    for (int it = 0; it < 8; it++) {
        int idx = base + it * 512 + threadIdx.x;
        if (idx < n) atomicAdd(&sh[(src[idx] >> shift) & 255u], 1u);
    }
    __syncthreads();
    if (threadIdx.x < 256) g_hist[threadIdx.x * nblk + blockIdx.x] = sh[threadIdx.x];
}

__global__ void k_histscanA(int nblk) {
    __shared__ unsigned shw[16];
    int bin = blockIdx.x, t = threadIdx.x, lane = t & 31, w = t >> 5;
    unsigned v = (t < nblk) ? g_hist[bin * nblk + t] : 0u;
    unsigned x = v;
    #pragma unroll
    for (int o = 1; o < 32; o <<= 1) { unsigned y = __shfl_up_sync(~0u, x, o); if (lane >= o) x += y; }
    if (lane == 31) shw[w] = x;
    __syncthreads();
    if (t < 16) {
        unsigned s = shw[t];
        #pragma unroll
        for (int o = 1; o < 16; o <<= 1) { unsigned y = __shfl_up_sync(0xFFFFu, s, o); if (t >= o) s += y; }
        shw[t] = s;
    }
    __syncthreads();
    unsigned excl = (w ? shw[w - 1] : 0u) + x - v;
    if (t < nblk) g_hist[bin * nblk + t] = excl;
    if (t == nblk - 1) g_binbase[bin] = excl + v;
}

__global__ void k_histscanB() {
    __shared__ unsigned shw[8];
    int t = threadIdx.x, lane = t & 31, w = t >> 5;
    unsigned v = g_binbase[t], x = v;
    #pragma unroll
    for (int o = 1; o < 32; o <<= 1) { unsigned y = __shfl_up_sync(~0u, x, o); if (lane >= o) x += y; }
    if (lane == 31) shw[w] = x;
    __syncthreads();
    if (t < 8) {
        unsigned s = shw[t];
        #pragma unroll
        for (int o = 1; o < 8; o <<= 1) { unsigned y = __shfl_up_sync(0xFFu, s, o); if (t >= o) s += y; }
        shw[t] = s;
    }
    __syncthreads();
    g_binbase[t] = (w ? shw[w - 1] : 0u) + x - v;
}

__global__ void k_scatter(int pass, int n, int nblk) {
    __shared__ unsigned warpHist[16][256];
    __shared__ unsigned binRun[256];
    __shared__ unsigned iterBase[256];
    const unsigned* src = (pass & 1) ? g_keyB : g_keyA;
    unsigned* dst = (pass & 1) ? g_keyA : g_keyB;
    int shift = pass * 8;
    int b = blockIdx.x, tid = threadIdx.x, w = tid >> 5, lane = tid & 31;
    for (int i = tid; i < 256; i += 512) binRun[i] = g_binbase[i] + g_hist[i * nblk + b];
    __syncthreads();
    int base = b * 4096;
    for (int it = 0; it < 8; it++) {
        for (int i = tid; i < 4096; i += 512) ((unsigned*)warpHist)[i] = 0u;
        __syncthreads();
        int idx = base + it * 512 + tid;
        bool valid = idx < n;
        unsigned key = valid ? src[idx] : 0u;
        unsigned d = (key >> shift) & 255u;
        unsigned vm = __ballot_sync(~0u, valid);
        unsigned mask = __match_any_sync(~0u, d) & vm;
        unsigned lrank = __popc(mask & ((1u << lane) - 1u));
        int leader = __ffs(mask) - 1;
        if (valid && lane == leader) warpHist[w][d] = __popc(mask);
        __syncthreads();
        if (tid < 256) {
            unsigned acc = 0;
            #pragma unroll
            for (int ww = 0; ww < 16; ww++) {
                unsigned tv = warpHist[ww][tid];
                warpHist[ww][tid] = acc;
                acc += tv;
            }
            iterBase[tid] = binRun[tid];
            binRun[tid] += acc;
        }
        __syncthreads();
        if (valid) dst[iterBase[d] + warpHist[w][d] + lrank] = key;
        __syncthreads();
    }
}

__global__ void k_median(float* out, long long V) {
    long long r = (long long)blockIdx.x * blockDim.x + threadIdx.x;
    if (r >= V) return;
    float mx = g_st.hmax;
    int pos = g_voffset[r] + (g_vcount[r] >> 1);
    float sv = fdec(g_keyA[pos]);
    out[51LL * V + r] = __fsub_rn(sv, __fmul_rn((float)r, mx));
}

extern "C" void kernel_launch(void* const* d_in, const int* in_sizes, int n_in,
                              void* d_out, int out_size) {
    const float* bxyz = (const float*)d_in[0];
    const float* feat = (const float*)d_in[1];
    const float* hh = (const float*)d_in[2];
    const float* vs = (const float*)d_in[3];
    int N = in_sizes[0] / 4;
    long long V = ((long long)out_size - 5LL * N) / 52LL;
    float* out = (float*)d_out;
    int NBC = (GRID_MAX + CPB - 1) / CPB;
    int NBV = (int)((V + CPB - 1) / CPB);
    int NBLK = (N + 4095) / 4096;

    k_init<<<1, 32>>>();
    k_zero_cells<<<2048, 256>>>();
    k_zero_out<<<2048, 256>>>(out + 15LL * V, 36LL * V);
    k_stats<<<2048, 256>>>((const float4*)bxyz, hh, N);
    k_vc<<<2048, 256>>>((const float4*)bxyz, vs, N);
    k_dims<<<1, 1>>>();
    k_merge<<<2048, 256>>>(out, V, N);
    k_scan_partial<<<NBC, 256>>>(0, 0);
    k_scan_bsums<<<1, 1024>>>(NBC);
    k_scan_final_cells<<<NBC, 256>>>();
    k_scan_partial<<<NBV, 256>>>(1, (int)V);
    k_scan_bsums<<<1, 1024>>>(NBV);
    k_scan_final_vox<<<NBV, 256>>>((int)V);
    k_accum<<<(N + 7) / 8, 256>>>(bxyz, feat, out, V, N);
    k_voxfin<<<(int)((V * 32 + 255) / 256), 256>>>(out, vs, V);
    k_tval<<<2048, 256>>>(hh, out, N, V);
    for (int p = 0; p < 4; p++) {
        k_hist<<<NBLK, 512>>>(p, N, NBLK);
        k_histscanA<<<256, 512>>>(NBLK);
        k_histscanB<<<1, 256>>>();
        k_scatter<<<NBLK, 512>>>(p, N, NBLK);
    }
    k_median<<<(int)((V + 255) / 256), 256>>>(out, V);
}

// round 4
// speedup vs baseline: 1.0478x; 1.0478x over previous
#include <cuda_runtime.h>

#define NMAX 2000128
#define GRID_MAX 34000000
#define NW (GRID_MAX / 32)
#define WPB 8192
#define CPB 8192

__device__ int g_cell[GRID_MAX];        // rank per occupied cell (write-before-read)
__device__ unsigned g_bits[NW];         // occupancy bitmask (memset 0 each launch)
__device__ int g_merge[NMAX];           // cell id, then rank
__device__ ushort4 g_vc[NMAX];
__device__ unsigned g_keyA[NMAX];       // encoded tvals binned by voxel (contiguous groups)
__device__ int g_vcount[NMAX];
__device__ int g_voffset[NMAX];
__device__ int g_cellof[NMAX];
__device__ int g_cursor[NMAX];
__device__ int g_bsums[8448];

struct Stats {
    unsigned pcmin_bits[4];
    unsigned hmin_e, hmax_e;
    int vcmax[4];
    int dims[4];
    float hmin, hmax;
    int wwin;
};
__device__ Stats g_st;

__device__ __forceinline__ unsigned fenc(float f) {
    unsigned b = __float_as_uint(f);
    return (b & 0x80000000u) ? ~b : (b | 0x80000000u);
}
__device__ __forceinline__ float fdec(unsigned u) {
    return __uint_as_float((u & 0x80000000u) ? (u ^ 0x80000000u) : ~u);
}

__global__ void k_init() {
    int t = threadIdx.x;
    if (t < 4) {
        g_st.pcmin_bits[t] = 0x7F800000u;
        g_st.vcmax[t] = (int)0x80000000;
    }
    if (t == 4) { g_st.hmin_e = 0xFFFFFFFFu; g_st.hmax_e = 0u; }
}

__global__ void k_stats(const float4* __restrict__ bxyz, const float* __restrict__ h, int n) {
    int tid = blockIdx.x * blockDim.x + threadIdx.x;
    int stride = gridDim.x * blockDim.x;
    float m0 = 3.4e38f, m1 = 3.4e38f, m2 = 3.4e38f, m3 = 3.4e38f;
    unsigned he0 = 0xFFFFFFFFu, he1 = 0u;
    int i = tid;
    for (; i + 3 * stride < n; i += 4 * stride) {
        float4 p0 = __ldg(&bxyz[i]);
        float4 p1 = __ldg(&bxyz[i + stride]);
        float4 p2 = __ldg(&bxyz[i + 2 * stride]);
        float4 p3 = __ldg(&bxyz[i + 3 * stride]);
        float h0 = __ldg(&h[i]), h1 = __ldg(&h[i + stride]);
        float h2 = __ldg(&h[i + 2 * stride]), h3 = __ldg(&h[i + 3 * stride]);
        m0 = fminf(m0, fminf(fminf(p0.x, p1.x), fminf(p2.x, p3.x)));
        m1 = fminf(m1, fminf(fminf(p0.y, p1.y), fminf(p2.y, p3.y)));
        m2 = fminf(m2, fminf(fminf(p0.z, p1.z), fminf(p2.z, p3.z)));
        m3 = fminf(m3, fminf(fminf(p0.w, p1.w), fminf(p2.w, p3.w)));
        unsigned e0 = fenc(h0), e1 = fenc(h1), e2 = fenc(h2), e3 = fenc(h3);
        he0 = min(he0, min(min(e0, e1), min(e2, e3)));
        he1 = max(he1, max(max(e0, e1), max(e2, e3)));
    }
    for (; i < n; i += stride) {
        float4 p = __ldg(&bxyz[i]);
        m0 = fminf(m0, p.x); m1 = fminf(m1, p.y);
        m2 = fminf(m2, p.z); m3 = fminf(m3, p.w);
        unsigned e = fenc(__ldg(&h[i]));
        he0 = min(he0, e); he1 = max(he1, e);
    }
    #pragma unroll
    for (int o = 16; o; o >>= 1) {
        m0 = fminf(m0, __shfl_down_sync(~0u, m0, o));
        m1 = fminf(m1, __shfl_down_sync(~0u, m1, o));
        m2 = fminf(m2, __shfl_down_sync(~0u, m2, o));
        m3 = fminf(m3, __shfl_down_sync(~0u, m3, o));
        he0 = min(he0, __shfl_down_sync(~0u, he0, o));
        he1 = max(he1, __shfl_down_sync(~0u, he1, o));
    }
    if ((threadIdx.x & 31) == 0) {
        atomicMin(&g_st.pcmin_bits[0], __float_as_uint(m0));
        atomicMin(&g_st.pcmin_bits[1], __float_as_uint(m1));
        atomicMin(&g_st.pcmin_bits[2], __float_as_uint(m2));
        atomicMin(&g_st.pcmin_bits[3], __float_as_uint(m3));
        atomicMin(&g_st.hmin_e, he0);
        atomicMax(&g_st.hmax_e, he1);
    }
}

__device__ __forceinline__ ushort4 vc_one(float4 p, float mn0, float mn1, float mn2, float mn3,
                                          float v0, float v1, float v2, float v3,
                                          int& b0, int& b1, int& b2, int& b3) {
    int c0 = (int)floorf(__fdiv_rn(__fsub_rn(p.x, mn0), v0));
    int c1 = (int)floorf(__fdiv_rn(__fsub_rn(p.y, mn1), v1));
    int c2 = (int)floorf(__fdiv_rn(__fsub_rn(p.z, mn2), v2));
    int c3 = (int)floorf(__fdiv_rn(__fsub_rn(p.w, mn3), v3));
    b0 = max(b0, c0); b1 = max(b1, c1); b2 = max(b2, c2); b3 = max(b3, c3);
    return make_ushort4((unsigned short)c0, (unsigned short)c1,
                        (unsigned short)c2, (unsigned short)c3);
}

__global__ void k_vc(const float4* __restrict__ bxyz, const float* __restrict__ vs, int n) {
    float mn0 = __uint_as_float(g_st.pcmin_bits[0]);
    float mn1 = __uint_as_float(g_st.pcmin_bits[1]);
    float mn2 = __uint_as_float(g_st.pcmin_bits[2]);
    float mn3 = __uint_as_float(g_st.pcmin_bits[3]);
    float v0 = __ldg(&vs[0]), v1 = __ldg(&vs[1]), v2 = __ldg(&vs[2]), v3 = __ldg(&vs[3]);
    int b0 = (int)0x80000000, b1 = b0, b2 = b0, b3 = b0;
    int tid = blockIdx.x * blockDim.x + threadIdx.x;
    int stride = gridDim.x * blockDim.x;
    int i = tid;
    for (; i + 3 * stride < n; i += 4 * stride) {
        float4 p0 = __ldg(&bxyz[i]);
        float4 p1 = __ldg(&bxyz[i + stride]);
        float4 p2 = __ldg(&bxyz[i + 2 * stride]);
        float4 p3 = __ldg(&bxyz[i + 3 * stride]);
        g_vc[i] = vc_one(p0, mn0, mn1, mn2, mn3, v0, v1, v2, v3, b0, b1, b2, b3);
        g_vc[i + stride] = vc_one(p1, mn0, mn1, mn2, mn3, v0, v1, v2, v3, b0, b1, b2, b3);
        g_vc[i + 2 * stride] = vc_one(p2, mn0, mn1, mn2, mn3, v0, v1, v2, v3, b0, b1, b2, b3);
        g_vc[i + 3 * stride] = vc_one(p3, mn0, mn1, mn2, mn3, v0, v1, v2, v3, b0, b1, b2, b3);
    }
    for (; i < n; i += stride) {
        float4 p = __ldg(&bxyz[i]);
        g_vc[i] = vc_one(p, mn0, mn1, mn2, mn3, v0, v1, v2, v3, b0, b1, b2, b3);
    }
    #pragma unroll
    for (int o = 16; o; o >>= 1) {
        b0 = max(b0, __shfl_down_sync(~0u, b0, o));
        b1 = max(b1, __shfl_down_sync(~0u, b1, o));
        b2 = max(b2, __shfl_down_sync(~0u, b2, o));
        b3 = max(b3, __shfl_down_sync(~0u, b3, o));
    }
    if ((threadIdx.x & 31) == 0) {
        atomicMax(&g_st.vcmax[0], b0);
        atomicMax(&g_st.vcmax[1], b1);
        atomicMax(&g_st.vcmax[2], b2);
        atomicMax(&g_st.vcmax[3], b3);
    }
}

__global__ void k_dims() {
    for (int k = 0; k < 4; k++) g_st.dims[k] = g_st.vcmax[k] + 1;   // vc.min == 0 exactly
    float mn = fdec(g_st.hmin_e), mx = fdec(g_st.hmax_e);
    g_st.hmin = mn;
    g_st.hmax = mx;
    int w = 64;
    if (mx > 0.0f) {
        float span = mx - mn;
        float ratio = span / mx;
        if (ratio < 60.0f) w = (int)ratio + 2;
    }
    g_st.wwin = w;
}

__global__ void k_merge(float* __restrict__ out, long long V, int n) {
    int d1 = g_st.dims[1], d2 = g_st.dims[2], d3 = g_st.dims[3];
    long long O9 = 52LL * V + n;
    int tid = blockIdx.x * blockDim.x + threadIdx.x;
    int stride = gridDim.x * blockDim.x;
    for (int i = tid; i < n; i += stride) {
        ushort4 v = g_vc[i];
        int c0 = v.x, c1 = v.y, c2 = v.z, c3 = v.w;
        int m = ((c0 * d1 + c1) * d2 + c2) * d3 + c3;
        g_merge[i] = m;
        atomicOr(&g_bits[m >> 5], 1u << (m & 31));
        *(float4*)&out[O9 + 4LL * i] = make_float4((float)c0, (float)c1, (float)c2, (float)c3);
    }
}

__device__ __forceinline__ int blockScanExcl256(int v, int* shw, int& total) {
    int lane = threadIdx.x & 31, w = threadIdx.x >> 5;
    int x = v;
    #pragma unroll
    for (int o = 1; o < 32; o <<= 1) { int y = __shfl_up_sync(~0u, x, o); if (lane >= o) x += y; }
    if (lane == 31) shw[w] = x;
    __syncthreads();
    if (threadIdx.x < 8) {
        int s = shw[threadIdx.x];
        #pragma unroll
        for (int o = 1; o < 8; o <<= 1) { int y = __shfl_up_sync(0xFFu, s, o); if ((int)threadIdx.x >= o) s += y; }
        shw[threadIdx.x] = s;
    }
    __syncthreads();
    int excl = (w ? shw[w - 1] : 0) + x - v;
    total = shw[7];
    __syncthreads();
    return excl;
}

__global__ void k_bits_partial() {
    __shared__ int shw[8];
    int base = blockIdx.x * WPB;
    int s = 0;
    for (int it = 0; it < WPB / 256; it++) {
        int idx = base + it * 256 + threadIdx.x;
        if (idx < NW) s += __popc(g_bits[idx]);
    }
    #pragma unroll
    for (int o = 16; o; o >>= 1) s += __shfl_down_sync(~0u, s, o);
    if ((threadIdx.x & 31) == 0) shw[threadIdx.x >> 5] = s;
    __syncthreads();
    if (threadIdx.x == 0) {
        int t = 0;
        for (int k = 0; k < 8; k++) t += shw[k];
        g_bsums[blockIdx.x] = t;
    }
}

__global__ void k_scan_bsums(int nb) {
    __shared__ int sh[32];
    int t = threadIdx.x, lane = t & 31, w = t >> 5;
    int c = (nb + 1023) / 1024;
    int loc[16];
    int s = 0;
    for (int j = 0; j < c; j++) {
        int idx = t * c + j;
        int v = (idx < nb) ? g_bsums[idx] : 0;
        loc[j] = s; s += v;
    }
    int x = s;
    #pragma unroll
    for (int o = 1; o < 32; o <<= 1) { int y = __shfl_up_sync(~0u, x, o); if (lane >= o) x += y; }
    if (lane == 31) sh[w] = x;
    __syncthreads();
    if (t < 32) {
        int v2 = sh[t];
        #pragma unroll
        for (int o = 1; o < 32; o <<= 1) { int y = __shfl_up_sync(~0u, v2, o); if (t >= o) v2 += y; }
        sh[t] = v2;
    }
    __syncthreads();
    int excl = (w ? sh[w - 1] : 0) + x - s;
    for (int j = 0; j < c; j++) {
        int idx = t * c + j;
        if (idx < nb) g_bsums[idx] = excl + loc[j];
    }
}

__global__ void k_bits_final() {
    __shared__ int shw[8];
    int start = blockIdx.x * WPB;
    int base = g_bsums[blockIdx.x];
    for (int it = 0; it < WPB / 256; it++) {
        int idx = start + it * 256 + threadIdx.x;
        unsigned w = (idx < NW) ? g_bits[idx] : 0u;
        int pc = __popc(w);
        int tot;
        int excl = blockScanExcl256(pc, shw, tot);
        int r = base + excl;
        while (w) {
            int j = __ffs(w) - 1;
            w &= w - 1;
            int cidx = idx * 32 + j;
            g_cell[cidx] = r;
            g_cellof[r] = cidx;
            r++;
        }
        base += tot;
    }
}

__global__ void k_accum(const float* __restrict__ bxyz, const float* __restrict__ feat,
                        float* __restrict__ out, long long V, int n) {
    int lane = threadIdx.x & 31;
    int warp = (blockIdx.x * blockDim.x + threadIdx.x) >> 5;
    int nwarps = (gridDim.x * blockDim.x) >> 5;
    for (int i = warp; i < n; i += nwarps) {
        int m = g_merge[i];
        int r = g_cell[m];
        float f = __ldg(&feat[(long long)i * 32 + lane]);
        atomicAdd(&out[19LL * V + (long long)r * 32 + lane], f);
        if (lane < 4) {
            float b = __ldg(&bxyz[(long long)i * 4 + lane]);
            atomicAdd(&out[15LL * V + (long long)r * 4 + lane], b);
        }
        if (lane == 0) {
            out[52LL * V + i] = (float)r;
            g_merge[i] = r;
            atomicAdd(&g_vcount[r], 1);
        }
    }
}

__global__ void k_vcount_partial(int nV) {
    __shared__ int shw[8];
    int base = blockIdx.x * CPB;
    int s = 0;
    for (int it = 0; it < CPB / 256; it++) {
        int idx = base + it * 256 + threadIdx.x;
        if (idx < nV) s += g_vcount[idx];
    }
    #pragma unroll
    for (int o = 16; o; o >>= 1) s += __shfl_down_sync(~0u, s, o);
    if ((threadIdx.x & 31) == 0) shw[threadIdx.x >> 5] = s;
    __syncthreads();
    if (threadIdx.x == 0) {
        int t = 0;
        for (int k = 0; k < 8; k++) t += shw[k];
        g_bsums[blockIdx.x] = t;
    }
}

__global__ void k_vcount_final(int nV) {
    __shared__ int shw[8];
    int start = blockIdx.x * CPB;
    int base = g_bsums[blockIdx.x];
    for (int it = 0; it < CPB / 256; it++) {
        int idx = start + it * 256 + threadIdx.x;
        int v = (idx < nV) ? g_vcount[idx] : 0;
        int tot;
        int excl = blockScanExcl256(v, shw, tot);
        if (idx < nV) g_voffset[idx] = base + excl;
        base += tot;
    }
}

__global__ void k_voxfin(float* __restrict__ out, const float* __restrict__ vs, long long V) {
    int lane = threadIdx.x & 31;
    long long warp = (long long)((blockIdx.x * blockDim.x + threadIdx.x) >> 5);
    long long nwarps = (long long)((gridDim.x * blockDim.x) >> 5);
    float vs1 = __ldg(&vs[1]), vs2 = __ldg(&vs[2]), vs3 = __ldg(&vs[3]);
    float mn1 = __uint_as_float(g_st.pcmin_bits[1]);
    float mn2 = __uint_as_float(g_st.pcmin_bits[2]);
    float mn3 = __uint_as_float(g_st.pcmin_bits[3]);
    int d1 = g_st.dims[1], d2 = g_st.dims[2], d3 = g_st.dims[3];
    for (long long r = warp; r < V; r += nwarps) {
        float fc = (float)g_vcount[r];
        long long o6 = 19LL * V + r * 32 + lane;
        out[o6] = __fdiv_rn(out[o6], fc);
        float mean = 0.0f;
        if (lane < 4) {
            long long o5 = 15LL * V + r * 4 + lane;
            mean = __fdiv_rn(out[o5], fc);
            out[o5] = mean;
        }
        float mb = __shfl_sync(~0u, mean, 0);
        float mx = __shfl_sync(~0u, mean, 1);
        float my = __shfl_sync(~0u, mean, 2);
        float mz = __shfl_sync(~0u, mean, 3);
        if (lane == 0) {
            int c = g_cellof[r];
            int c3 = c % d3; c /= d3;
            int c2 = c % d2; c /= d2;
            int c1 = c % d1;
            int c0 = c / d1;
            out[r] = (float)(int)rintf(mb);
            out[V + r * 3 + 0] = mx;
            out[V + r * 3 + 1] = my;
            out[V + r * 3 + 2] = mz;
            float t1 = __fadd_rn(__fmul_rn((float)c1, vs1), mn1);
            float t2 = __fadd_rn(__fmul_rn((float)c2, vs2), mn2);
            float t3 = __fadd_rn(__fmul_rn((float)c3, vs3), mn3);
            float ctr1 = __fadd_rn(t1, __fdiv_rn(vs1, 2.0f));
            float ctr2 = __fadd_rn(t2, __fdiv_rn(vs2, 2.0f));
            float ctr3 = __fadd_rn(t3, __fdiv_rn(vs3, 2.0f));
            out[4LL * V + r * 3 + 0] = ctr1;
            out[4LL * V + r * 3 + 1] = ctr2;
            out[4LL * V + r * 3 + 2] = ctr3;
            out[7LL * V + r * 4 + 0] = mb;
            out[7LL * V + r * 4 + 1] = ctr1;
            out[7LL * V + r * 4 + 2] = ctr2;
            out[7LL * V + r * 4 + 3] = ctr3;
            out[11LL * V + r * 4 + 0] = (float)c0;
            out[11LL * V + r * 4 + 1] = (float)c1;
            out[11LL * V + r * 4 + 2] = (float)c2;
            out[11LL * V + r * 4 + 3] = (float)c3;
        }
    }
}

__global__ void k_bin(const float* __restrict__ h, int n) {
    float mn = g_st.hmin, mx = g_st.hmax;
    int tid = blockIdx.x * blockDim.x + threadIdx.x;
    int stride = gridDim.x * blockDim.x;
    for (int i = tid; i < n; i += stride) {
        int r = g_merge[i];
        float t = __fadd_rn(__fsub_rn(__ldg(&h[i]), mn), __fmul_rn((float)r, mx));
        int pos = atomicAdd(&g_cursor[r], 1);
        g_keyA[g_voffset[r] + pos] = fenc(t);
    }
}

// Windowed exact selection: reproduces sorted_vals[offset_r + deg_r//2] of the
// GLOBAL sort. T is bracketed in [fl(r*max), fl(span+fl(r*max))]; only groups
// within +-W contribute there; groups are contiguous in g_keyA.
__global__ void k_median(float* __restrict__ out, long long V, int N) {
    long long r = (long long)blockIdx.x * blockDim.x + threadIdx.x;
    if (r >= V) return;
    float mx = g_st.hmax;
    int W = g_st.wwin;
    long long lo = r - W; if (lo < 0) lo = 0;
    long long hi = r + W; if (hi > V - 1) hi = V - 1;
    int s0 = g_voffset[lo];
    int sr = g_voffset[r];
    int s1 = (hi + 1 < V) ? g_voffset[hi + 1] : N;
    unsigned thr = fenc(__fmul_rn((float)r, mx));
    int p = sr + (g_vcount[r] >> 1);
    int low = s0;
    for (int j = s0; j < sr; j++)
        if (__ldg(&g_keyA[j]) < thr) low++;
    int kk = p - low;
    unsigned ans = 0u;
    for (int i = s0; i < s1; i++) {
        unsigned ki = __ldg(&g_keyA[i]);
        if (ki < thr) continue;
        int rank = 0;
        for (int j = s0; j < s1; j++) {
            unsigned kj = __ldg(&g_keyA[j]);
            if (kj < thr) continue;
            rank += (kj < ki) || (kj == ki && j < i);
        }
        if (rank == kk) { ans = ki; break; }
    }
    out[51LL * V + r] = __fsub_rn(fdec(ans), __fmul_rn((float)r, mx));
}

extern "C" void kernel_launch(void* const* d_in, const int* in_sizes, int n_in,
                              void* d_out, int out_size) {
    const float* bxyz = (const float*)d_in[0];
    const float* feat = (const float*)d_in[1];
    const float* hh = (const float*)d_in[2];
    const float* vs = (const float*)d_in[3];
    int N = in_sizes[0] / 4;
    long long V = ((long long)out_size - 5LL * N) / 52LL;
    float* out = (float*)d_out;

    void *p_bits = 0, *p_vcount = 0, *p_cursor = 0;
    cudaGetSymbolAddress(&p_bits, g_bits);
    cudaGetSymbolAddress(&p_vcount, g_vcount);
    cudaGetSymbolAddress(&p_cursor, g_cursor);

    int NBW = (NW + WPB - 1) / WPB;
    int NBV = (int)((V + CPB - 1) / CPB);

    cudaMemsetAsync(p_bits, 0, sizeof(unsigned) * NW);
    cudaMemsetAsync(p_vcount, 0, sizeof(int) * (size_t)V);
    cudaMemsetAsync(p_cursor, 0, sizeof(int) * (size_t)V);
    cudaMemsetAsync(out + 15LL * V, 0, sizeof(float) * (size_t)(36LL * V));

    k_init<<<1, 32>>>();
    k_stats<<<2048, 256>>>((const float4*)bxyz, hh, N);
    k_vc<<<2048, 256>>>((const float4*)bxyz, vs, N);
    k_dims<<<1, 1>>>();
    k_merge<<<2048, 256>>>(out, V, N);
    k_bits_partial<<<NBW, 256>>>();
    k_scan_bsums<<<1, 1024>>>(NBW);
    k_bits_final<<<NBW, 256>>>();
    k_accum<<<2048, 256>>>(bxyz, feat, out, V, N);
    k_vcount_partial<<<NBV, 256>>>((int)V);
    k_scan_bsums<<<1, 1024>>>(NBV);
    k_vcount_final<<<NBV, 256>>>((int)V);
    k_voxfin<<<2048, 256>>>(out, vs, V);
    k_bin<<<2048, 256>>>(hh, N);
    k_median<<<(int)((V + 255) / 256), 256>>>(out, V, N);
}

// round 5
// speedup vs baseline: 1.5236x; 1.4541x over previous
#include <cuda_runtime.h>

#define NMAX 2000128
#define GRID_MAX 34000000
#define NW (GRID_MAX / 32)
#define WPB 8192
#define CPB 8192

__device__ int g_cell[GRID_MAX];
__device__ unsigned g_bits[NW];
__device__ int g_merge[NMAX];
__device__ ushort4 g_vc[NMAX];
__device__ unsigned g_keyA[NMAX];
__device__ int g_vcount[NMAX];
__device__ int g_voffset[NMAX];
__device__ int g_cellof[NMAX];
__device__ int g_cursor[NMAX];
__device__ int g_bsums[8448];

struct Stats {
    unsigned pcmin_bits[4];
    unsigned hmin_e, hmax_e;
    int vcmax[4];
    int dims[4];
    float hmin, hmax;
    int wwin;
};
__device__ Stats g_st;

__device__ __forceinline__ unsigned fenc(float f) {
    unsigned b = __float_as_uint(f);
    return (b & 0x80000000u) ? ~b : (b | 0x80000000u);
}
__device__ __forceinline__ float fdec(unsigned u) {
    return __uint_as_float((u & 0x80000000u) ? (u ^ 0x80000000u) : ~u);
}

__global__ void k_init() {
    int t = threadIdx.x;
    if (t < 4) {
        g_st.pcmin_bits[t] = 0x7F800000u;
        g_st.vcmax[t] = (int)0x80000000;
    }
    if (t == 4) { g_st.hmin_e = 0xFFFFFFFFu; g_st.hmax_e = 0u; }
}

__global__ void k_stats(const float4* __restrict__ bxyz, const float* __restrict__ h, int n) {
    int tid = blockIdx.x * blockDim.x + threadIdx.x;
    int stride = gridDim.x * blockDim.x;
    float m0 = 3.4e38f, m1 = 3.4e38f, m2 = 3.4e38f, m3 = 3.4e38f;
    unsigned he0 = 0xFFFFFFFFu, he1 = 0u;
    int i = tid;
    for (; i + 3 * stride < n; i += 4 * stride) {
        float4 p0 = __ldg(&bxyz[i]);
        float4 p1 = __ldg(&bxyz[i + stride]);
        float4 p2 = __ldg(&bxyz[i + 2 * stride]);
        float4 p3 = __ldg(&bxyz[i + 3 * stride]);
        float h0 = __ldg(&h[i]), h1 = __ldg(&h[i + stride]);
        float h2 = __ldg(&h[i + 2 * stride]), h3 = __ldg(&h[i + 3 * stride]);
        m0 = fminf(m0, fminf(fminf(p0.x, p1.x), fminf(p2.x, p3.x)));
        m1 = fminf(m1, fminf(fminf(p0.y, p1.y), fminf(p2.y, p3.y)));
        m2 = fminf(m2, fminf(fminf(p0.z, p1.z), fminf(p2.z, p3.z)));
        m3 = fminf(m3, fminf(fminf(p0.w, p1.w), fminf(p2.w, p3.w)));
        unsigned e0 = fenc(h0), e1 = fenc(h1), e2 = fenc(h2), e3 = fenc(h3);
        he0 = min(he0, min(min(e0, e1), min(e2, e3)));
        he1 = max(he1, max(max(e0, e1), max(e2, e3)));
    }
    for (; i < n; i += stride) {
        float4 p = __ldg(&bxyz[i]);
        m0 = fminf(m0, p.x); m1 = fminf(m1, p.y);
        m2 = fminf(m2, p.z); m3 = fminf(m3, p.w);
        unsigned e = fenc(__ldg(&h[i]));
        he0 = min(he0, e); he1 = max(he1, e);
    }
    #pragma unroll
    for (int o = 16; o; o >>= 1) {
        m0 = fminf(m0, __shfl_down_sync(~0u, m0, o));
        m1 = fminf(m1, __shfl_down_sync(~0u, m1, o));
        m2 = fminf(m2, __shfl_down_sync(~0u, m2, o));
        m3 = fminf(m3, __shfl_down_sync(~0u, m3, o));
        he0 = min(he0, __shfl_down_sync(~0u, he0, o));
        he1 = max(he1, __shfl_down_sync(~0u, he1, o));
    }
    if ((threadIdx.x & 31) == 0) {
        atomicMin(&g_st.pcmin_bits[0], __float_as_uint(m0));
        atomicMin(&g_st.pcmin_bits[1], __float_as_uint(m1));
        atomicMin(&g_st.pcmin_bits[2], __float_as_uint(m2));
        atomicMin(&g_st.pcmin_bits[3], __float_as_uint(m3));
        atomicMin(&g_st.hmin_e, he0);
        atomicMax(&g_st.hmax_e, he1);
    }
}

__global__ void k_vc(const float4* __restrict__ bxyz, const float* __restrict__ vs, int n) {
    float mn0 = __uint_as_float(g_st.pcmin_bits[0]);
    float mn1 = __uint_as_float(g_st.pcmin_bits[1]);
    float mn2 = __uint_as_float(g_st.pcmin_bits[2]);
    float mn3 = __uint_as_float(g_st.pcmin_bits[3]);
    float v0 = __ldg(&vs[0]), v1 = __ldg(&vs[1]), v2 = __ldg(&vs[2]), v3 = __ldg(&vs[3]);
    int i = blockIdx.x * blockDim.x + threadIdx.x;
    if (i >= n) return;
    float4 p = __ldg(&bxyz[i]);
    int c0 = (int)floorf(__fdiv_rn(__fsub_rn(p.x, mn0), v0));
    int c1 = (int)floorf(__fdiv_rn(__fsub_rn(p.y, mn1), v1));
    int c2 = (int)floorf(__fdiv_rn(__fsub_rn(p.z, mn2), v2));
    int c3 = (int)floorf(__fdiv_rn(__fsub_rn(p.w, mn3), v3));
    g_vc[i] = make_ushort4((unsigned short)c0, (unsigned short)c1,
                           (unsigned short)c2, (unsigned short)c3);
    int b0 = c0, b1 = c1, b2 = c2, b3 = c3;
    #pragma unroll
    for (int o = 16; o; o >>= 1) {
        b0 = max(b0, __shfl_down_sync(~0u, b0, o));
        b1 = max(b1, __shfl_down_sync(~0u, b1, o));
        b2 = max(b2, __shfl_down_sync(~0u, b2, o));
        b3 = max(b3, __shfl_down_sync(~0u, b3, o));
    }
    if ((threadIdx.x & 31) == 0) {
        atomicMax(&g_st.vcmax[0], b0);
        atomicMax(&g_st.vcmax[1], b1);
        atomicMax(&g_st.vcmax[2], b2);
        atomicMax(&g_st.vcmax[3], b3);
    }
}

__global__ void k_dims() {
    for (int k = 0; k < 4; k++) g_st.dims[k] = g_st.vcmax[k] + 1;   // vc.min == 0 exactly
    float mn = fdec(g_st.hmin_e), mx = fdec(g_st.hmax_e);
    g_st.hmin = mn;
    g_st.hmax = mx;
    int w = 64;
    if (mx > 0.0f) {
        float ratio = (mx - mn) / mx;
        if (ratio < 60.0f) w = (int)ratio + 2;
    }
    g_st.wwin = w;
}

__global__ void k_merge(float* __restrict__ out, long long V, int n) {
    int d1 = g_st.dims[1], d2 = g_st.dims[2], d3 = g_st.dims[3];
    long long O9 = 52LL * V + n;
    int i = blockIdx.x * blockDim.x + threadIdx.x;
    if (i >= n) return;
    ushort4 v = g_vc[i];
    int c0 = v.x, c1 = v.y, c2 = v.z, c3 = v.w;
    int m = ((c0 * d1 + c1) * d2 + c2) * d3 + c3;
    g_merge[i] = m;
    atomicOr(&g_bits[m >> 5], 1u << (m & 31));
    *(float4*)&out[O9 + 4LL * i] = make_float4((float)c0, (float)c1, (float)c2, (float)c3);
}

__device__ __forceinline__ int blockScanExcl256(int v, int* shw, int& total) {
    int lane = threadIdx.x & 31, w = threadIdx.x >> 5;
    int x = v;
    #pragma unroll
    for (int o = 1; o < 32; o <<= 1) { int y = __shfl_up_sync(~0u, x, o); if (lane >= o) x += y; }
    if (lane == 31) shw[w] = x;
    __syncthreads();
    if (threadIdx.x < 8) {
        int s = shw[threadIdx.x];
        #pragma unroll
        for (int o = 1; o < 8; o <<= 1) { int y = __shfl_up_sync(0xFFu, s, o); if ((int)threadIdx.x >= o) s += y; }
        shw[threadIdx.x] = s;
    }
    __syncthreads();
    int excl = (w ? shw[w - 1] : 0) + x - v;
    total = shw[7];
    __syncthreads();
    return excl;
}

__global__ void k_bits_partial() {
    __shared__ int shw[8];
    int base = blockIdx.x * WPB;
    int s = 0;
    for (int it = 0; it < WPB / 256; it++) {
        int idx = base + it * 256 + threadIdx.x;
        if (idx < NW) s += __popc(g_bits[idx]);
    }
    #pragma unroll
    for (int o = 16; o; o >>= 1) s += __shfl_down_sync(~0u, s, o);
    if ((threadIdx.x & 31) == 0) shw[threadIdx.x >> 5] = s;
    __syncthreads();
    if (threadIdx.x == 0) {
        int t = 0;
        for (int k = 0; k < 8; k++) t += shw[k];
        g_bsums[blockIdx.x] = t;
    }
}

__global__ void k_scan_bsums(int nb) {
    __shared__ int sh[32];
    int t = threadIdx.x, lane = t & 31, w = t >> 5;
    int c = (nb + 1023) / 1024;
    int loc[16];
    int s = 0;
    for (int j = 0; j < c; j++) {
        int idx = t * c + j;
        int v = (idx < nb) ? g_bsums[idx] : 0;
        loc[j] = s; s += v;
    }
    int x = s;
    #pragma unroll
    for (int o = 1; o < 32; o <<= 1) { int y = __shfl_up_sync(~0u, x, o); if (lane >= o) x += y; }
    if (lane == 31) sh[w] = x;
    __syncthreads();
    if (t < 32) {
        int v2 = sh[t];
        #pragma unroll
        for (int o = 1; o < 32; o <<= 1) { int y = __shfl_up_sync(~0u, v2, o); if (t >= o) v2 += y; }
        sh[t] = v2;
    }
    __syncthreads();
    int excl = (w ? sh[w - 1] : 0) + x - s;
    for (int j = 0; j < c; j++) {
        int idx = t * c + j;
        if (idx < nb) g_bsums[idx] = excl + loc[j];
    }
}

__global__ void k_bits_final() {
    __shared__ int shw[8];
    int start = blockIdx.x * WPB;
    int base = g_bsums[blockIdx.x];
    for (int it = 0; it < WPB / 256; it++) {
        int idx = start + it * 256 + threadIdx.x;
        unsigned w = (idx < NW) ? g_bits[idx] : 0u;
        int pc = __popc(w);
        int tot;
        int excl = blockScanExcl256(pc, shw, tot);
        int r = base + excl;
        while (w) {
            int j = __ffs(w) - 1;
            w &= w - 1;
            int cidx = idx * 32 + j;
            g_cell[cidx] = r;
            g_cellof[r] = cidx;
            r++;
        }
        base += tot;
    }
}

// thread per point: rank lookup, voxel_index output, count
__global__ void k_count(float* __restrict__ out, long long V, int n) {
    int i = blockIdx.x * blockDim.x + threadIdx.x;
    if (i >= n) return;
    int r = g_cell[g_merge[i]];
    g_merge[i] = r;
    out[52LL * V + i] = (float)r;
    atomicAdd(&g_vcount[r], 1);
}

__global__ void k_vcount_partial(int nV) {
    __shared__ int shw[8];
    int base = blockIdx.x * CPB;
    int s = 0;
    for (int it = 0; it < CPB / 256; it++) {
        int idx = base + it * 256 + threadIdx.x;
        if (idx < nV) s += g_vcount[idx];
    }
    #pragma unroll
    for (int o = 16; o; o >>= 1) s += __shfl_down_sync(~0u, s, o);
    if ((threadIdx.x & 31) == 0) shw[threadIdx.x >> 5] = s;
    __syncthreads();
    if (threadIdx.x == 0) {
        int t = 0;
        for (int k = 0; k < 8; k++) t += shw[k];
        g_bsums[blockIdx.x] = t;
    }
}

__global__ void k_vcount_final(int nV) {
    __shared__ int shw[8];
    int start = blockIdx.x * CPB;
    int base = g_bsums[blockIdx.x];
    for (int it = 0; it < CPB / 256; it++) {
        int idx = start + it * 256 + threadIdx.x;
        int v = (idx < nV) ? g_vcount[idx] : 0;
        int tot;
        int excl = blockScanExcl256(v, shw, tot);
        if (idx < nV) g_voffset[idx] = base + excl;
        base += tot;
    }
}

// zero accumulators ONLY for multi-count voxels (~3%)
__global__ void k_zero_multi(float* __restrict__ out, long long V) {
    long long r = (long long)blockIdx.x * blockDim.x + threadIdx.x;
    if (r >= V) return;
    if (g_vcount[r] > 1) {
        *(float4*)&out[15LL * V + r * 4] = make_float4(0.f, 0.f, 0.f, 0.f);
        float4 z = make_float4(0.f, 0.f, 0.f, 0.f);
        float4* fp = (float4*)&out[19LL * V + r * 32];
        #pragma unroll
        for (int k = 0; k < 8; k++) fp[k] = z;
        g_cursor[r] = 0;
    }
}

// warp per point: feat + bxyz accumulate (plain store for count==1) + median key bin
__global__ void k_accum2(const float* __restrict__ bxyz, const float* __restrict__ feat,
                         const float* __restrict__ h, float* __restrict__ out,
                         long long V, int n) {
    int lane = threadIdx.x & 31;
    int i = (blockIdx.x * blockDim.x + threadIdx.x) >> 5;
    if (i >= n) return;
    int r = g_merge[i];
    int c = g_vcount[r];
    float f = __ldg(&feat[(long long)i * 32 + lane]);
    long long fo = 19LL * V + (long long)r * 32 + lane;
    if (c == 1) out[fo] = f;
    else atomicAdd(&out[fo], f);
    if (lane < 4) {
        float b = __ldg(&bxyz[(long long)i * 4 + lane]);
        long long bo = 15LL * V + (long long)r * 4 + lane;
        if (c == 1) out[bo] = b;
        else atomicAdd(&out[bo], b);
    }
    if (lane == 0) {
        float tv = __fadd_rn(__fsub_rn(__ldg(&h[i]), g_st.hmin), __fmul_rn((float)r, g_st.hmax));
        int pos = (c == 1) ? 0 : atomicAdd(&g_cursor[r], 1);
        g_keyA[g_voffset[r] + pos] = fenc(tv);
    }
}

// thread per voxel: coalesced scalar outputs
__global__ void k_voxfin_scalar(float* __restrict__ out, const float* __restrict__ vs, long long V) {
    long long r = (long long)blockIdx.x * blockDim.x + threadIdx.x;
    if (r >= V) return;
    float vs1 = __ldg(&vs[1]), vs2 = __ldg(&vs[2]), vs3 = __ldg(&vs[3]);
    float mn1 = __uint_as_float(g_st.pcmin_bits[1]);
    float mn2 = __uint_as_float(g_st.pcmin_bits[2]);
    float mn3 = __uint_as_float(g_st.pcmin_bits[3]);
    int d1 = g_st.dims[1], d2 = g_st.dims[2], d3 = g_st.dims[3];
    int c = g_vcount[r];
    float4 s = *(float4*)&out[15LL * V + r * 4];
    if (c > 1) {
        float fc = (float)c;
        s.x = __fdiv_rn(s.x, fc);
        s.y = __fdiv_rn(s.y, fc);
        s.z = __fdiv_rn(s.z, fc);
        s.w = __fdiv_rn(s.w, fc);
        *(float4*)&out[15LL * V + r * 4] = s;
    }
    int cell = g_cellof[r];
    int c3 = cell % d3; cell /= d3;
    int c2 = cell % d2; cell /= d2;
    int c1 = cell % d1;
    int c0 = cell / d1;
    out[r] = (float)(int)rintf(s.x);
    out[V + r * 3 + 0] = s.y;
    out[V + r * 3 + 1] = s.z;
    out[V + r * 3 + 2] = s.w;
    float t1 = __fadd_rn(__fmul_rn((float)c1, vs1), mn1);
    float t2 = __fadd_rn(__fmul_rn((float)c2, vs2), mn2);
    float t3 = __fadd_rn(__fmul_rn((float)c3, vs3), mn3);
    float ctr1 = __fadd_rn(t1, __fdiv_rn(vs1, 2.0f));
    float ctr2 = __fadd_rn(t2, __fdiv_rn(vs2, 2.0f));
    float ctr3 = __fadd_rn(t3, __fdiv_rn(vs3, 2.0f));
    out[4LL * V + r * 3 + 0] = ctr1;
    out[4LL * V + r * 3 + 1] = ctr2;
    out[4LL * V + r * 3 + 2] = ctr3;
    *(float4*)&out[7LL * V + r * 4] = make_float4(s.x, ctr1, ctr2, ctr3);
    *(float4*)&out[11LL * V + r * 4] = make_float4((float)c0, (float)c1, (float)c2, (float)c3);
}

// warp per voxel: feat divide, only count>1
__global__ void k_voxfin_feat(float* __restrict__ out, long long V) {
    int lane = threadIdx.x & 31;
    long long r = (long long)((blockIdx.x * blockDim.x + threadIdx.x) >> 5);
    if (r >= V) return;
    int c = g_vcount[r];
    if (c <= 1) return;
    float fc = (float)c;
    long long o = 19LL * V + r * 32 + lane;
    out[o] = __fdiv_rn(out[o], fc);
}

// windowed exact selection over the (virtual) global sort — identical to R4 (passed)
__global__ void k_median(float* __restrict__ out, long long V, int N) {
    long long r = (long long)blockIdx.x * blockDim.x + threadIdx.x;
    if (r >= V) return;
    float mx = g_st.hmax;
    int W = g_st.wwin;
    long long lo = r - W; if (lo < 0) lo = 0;
    long long hi = r + W; if (hi > V - 1) hi = V - 1;
    int s0 = g_voffset[lo];
    int sr = g_voffset[r];
    int s1 = (hi + 1 < V) ? g_voffset[hi + 1] : N;
    unsigned thr = fenc(__fmul_rn((float)r, mx));
    int p = sr + (g_vcount[r] >> 1);
    int low = s0;
    for (int j = s0; j < sr; j++)
        if (__ldg(&g_keyA[j]) < thr) low++;
    int kk = p - low;
    unsigned ans = 0u;
    for (int i = s0; i < s1; i++) {
        unsigned ki = __ldg(&g_keyA[i]);
        if (ki < thr) continue;
        int rank = 0;
        for (int j = s0; j < s1; j++) {
            unsigned kj = __ldg(&g_keyA[j]);
            if (kj < thr) continue;
            rank += (kj < ki) || (kj == ki && j < i);
        }
        if (rank == kk) { ans = ki; break; }
    }
    out[51LL * V + r] = __fsub_rn(fdec(ans), __fmul_rn((float)r, mx));
}

extern "C" void kernel_launch(void* const* d_in, const int* in_sizes, int n_in,
                              void* d_out, int out_size) {
    const float* bxyz = (const float*)d_in[0];
    const float* feat = (const float*)d_in[1];
    const float* hh = (const float*)d_in[2];
    const float* vs = (const float*)d_in[3];
    int N = in_sizes[0] / 4;
    long long V = ((long long)out_size - 5LL * N) / 52LL;
    float* out = (float*)d_out;

    void *p_bits = 0, *p_vcount = 0;
    cudaGetSymbolAddress(&p_bits, g_bits);
    cudaGetSymbolAddress(&p_vcount, g_vcount);

    int NBW = (NW + WPB - 1) / WPB;
    int NBV = (int)((V + CPB - 1) / CPB);
    int BPT = (N + 255) / 256;                       // thread-per-point blocks
    int BWP = (int)(((long long)N * 32 + 255) / 256); // warp-per-point blocks
    int BVT = (int)((V + 255) / 256);                // thread-per-voxel blocks
    int BVW = (int)((V * 32 + 255) / 256);           // warp-per-voxel blocks

    cudaMemsetAsync(p_bits, 0, sizeof(unsigned) * NW);
    cudaMemsetAsync(p_vcount, 0, sizeof(int) * (size_t)V);

    k_init<<<1, 32>>>();
    k_stats<<<2048, 256>>>((const float4*)bxyz, hh, N);
    k_vc<<<BPT, 256>>>((const float4*)bxyz, vs, N);
    k_dims<<<1, 1>>>();
    k_merge<<<BPT, 256>>>(out, V, N);
    k_bits_partial<<<NBW, 256>>>();
    k_scan_bsums<<<1, 1024>>>(NBW);
    k_bits_final<<<NBW, 256>>>();
    k_count<<<BPT, 256>>>(out, V, N);
    k_vcount_partial<<<NBV, 256>>>((int)V);
    k_scan_bsums<<<1, 1024>>>(NBV);
    k_vcount_final<<<NBV, 256>>>((int)V);
    k_zero_multi<<<BVT, 256>>>(out, V);
    k_accum2<<<BWP, 256>>>(bxyz, feat, hh, out, V, N);
    k_voxfin_scalar<<<BVT, 256>>>(out, vs, V);
    k_voxfin_feat<<<BVW, 256>>>(out, V);
    k_median<<<BVT, 256>>>(out, V, N);
}

// round 6
// speedup vs baseline: 2.3385x; 1.5349x over previous
#include <cuda_runtime.h>

#define NMAX 2000128
#define NKEY (1 << 26)
#define NWRD (NKEY / 32)
#define WPB 8192
#define CPB 8192

__device__ uint2 g_w[NWRD];             // {occupancy mask, exclusive rank prefix}
__device__ int g_merge[NMAX];           // bitfield key, then rank
__device__ unsigned g_keyA[NMAX];       // encoded tvals binned by voxel
__device__ int g_vcount[NMAX];
__device__ int g_voffset[NMAX];
__device__ int g_cellof[NMAX];          // rank -> bitfield key
__device__ int g_cursor[NMAX];
__device__ int g_bsums[8448];
__device__ int g_multilist[NMAX];
__device__ int g_nmulti;

struct Stats {
    unsigned pcmin_bits[4];
    unsigned hmin_e, hmax_e;
    float hmin, hmax;
    int wwin;
};
__device__ Stats g_st;

__device__ __forceinline__ unsigned fenc(float f) {
    unsigned b = __float_as_uint(f);
    return (b & 0x80000000u) ? ~b : (b | 0x80000000u);
}
__device__ __forceinline__ float fdec(unsigned u) {
    return __uint_as_float((u & 0x80000000u) ? (u ^ 0x80000000u) : ~u);
}

__global__ void k_init() {
    int t = threadIdx.x;
    if (t < 4) g_st.pcmin_bits[t] = 0x7F800000u;
    if (t == 4) { g_st.hmin_e = 0xFFFFFFFFu; g_st.hmax_e = 0u; g_nmulti = 0; }
}

__global__ void k_stats(const float4* __restrict__ bxyz, const float* __restrict__ h, int n) {
    int tid = blockIdx.x * blockDim.x + threadIdx.x;
    int stride = gridDim.x * blockDim.x;
    float m0 = 3.4e38f, m1 = 3.4e38f, m2 = 3.4e38f, m3 = 3.4e38f;
    unsigned he0 = 0xFFFFFFFFu, he1 = 0u;
    int i = tid;
    for (; i + 3 * stride < n; i += 4 * stride) {
        float4 p0 = __ldg(&bxyz[i]);
        float4 p1 = __ldg(&bxyz[i + stride]);
        float4 p2 = __ldg(&bxyz[i + 2 * stride]);
        float4 p3 = __ldg(&bxyz[i + 3 * stride]);
        float h0 = __ldg(&h[i]), h1 = __ldg(&h[i + stride]);
        float h2 = __ldg(&h[i + 2 * stride]), h3 = __ldg(&h[i + 3 * stride]);
        m0 = fminf(m0, fminf(fminf(p0.x, p1.x), fminf(p2.x, p3.x)));
        m1 = fminf(m1, fminf(fminf(p0.y, p1.y), fminf(p2.y, p3.y)));
        m2 = fminf(m2, fminf(fminf(p0.z, p1.z), fminf(p2.z, p3.z)));
        m3 = fminf(m3, fminf(fminf(p0.w, p1.w), fminf(p2.w, p3.w)));
        unsigned e0 = fenc(h0), e1 = fenc(h1), e2 = fenc(h2), e3 = fenc(h3);
        he0 = min(he0, min(min(e0, e1), min(e2, e3)));
        he1 = max(he1, max(max(e0, e1), max(e2, e3)));
    }
    for (; i < n; i += stride) {
        float4 p = __ldg(&bxyz[i]);
        m0 = fminf(m0, p.x); m1 = fminf(m1, p.y);
        m2 = fminf(m2, p.z); m3 = fminf(m3, p.w);
        unsigned e = fenc(__ldg(&h[i]));
        he0 = min(he0, e); he1 = max(he1, e);
    }
    #pragma unroll
    for (int o = 16; o; o >>= 1) {
        m0 = fminf(m0, __shfl_down_sync(~0u, m0, o));
        m1 = fminf(m1, __shfl_down_sync(~0u, m1, o));
        m2 = fminf(m2, __shfl_down_sync(~0u, m2, o));
        m3 = fminf(m3, __shfl_down_sync(~0u, m3, o));
        he0 = min(he0, __shfl_down_sync(~0u, he0, o));
        he1 = max(he1, __shfl_down_sync(~0u, he1, o));
    }
    if ((threadIdx.x & 31) == 0) {
        atomicMin(&g_st.pcmin_bits[0], __float_as_uint(m0));
        atomicMin(&g_st.pcmin_bits[1], __float_as_uint(m1));
        atomicMin(&g_st.pcmin_bits[2], __float_as_uint(m2));
        atomicMin(&g_st.pcmin_bits[3], __float_as_uint(m3));
        atomicMin(&g_st.hmin_e, he0);
        atomicMax(&g_st.hmax_e, he1);
    }
}

__global__ void k_small() {
    float mn = fdec(g_st.hmin_e), mx = fdec(g_st.hmax_e);
    g_st.hmin = mn;
    g_st.hmax = mx;
    int w = 64;
    if (mx > 0.0f) {
        float ratio = (mx - mn) / mx;
        if (ratio < 60.0f) w = (int)ratio + 2;
    }
    g_st.wwin = w;
}

// fused: coords + bitfield key + occupancy + point_coords output
__global__ void k_merge(const float4* __restrict__ bxyz, const float* __restrict__ vs,
                        float* __restrict__ out, long long V, int n) {
    float mn0 = __uint_as_float(g_st.pcmin_bits[0]);
    float mn1 = __uint_as_float(g_st.pcmin_bits[1]);
    float mn2 = __uint_as_float(g_st.pcmin_bits[2]);
    float mn3 = __uint_as_float(g_st.pcmin_bits[3]);
    float v0 = __ldg(&vs[0]), v1 = __ldg(&vs[1]), v2 = __ldg(&vs[2]), v3 = __ldg(&vs[3]);
    long long O9 = 52LL * V + n;
    int i = blockIdx.x * blockDim.x + threadIdx.x;
    if (i >= n) return;
    float4 p = __ldg(&bxyz[i]);
    int c0 = (int)floorf(__fdiv_rn(__fsub_rn(p.x, mn0), v0));
    int c1 = (int)floorf(__fdiv_rn(__fsub_rn(p.y, mn1), v1));
    int c2 = (int)floorf(__fdiv_rn(__fsub_rn(p.z, mn2), v2));
    int c3 = (int)floorf(__fdiv_rn(__fsub_rn(p.w, mn3), v3));
    int key = (c0 << 24) | (c1 << 16) | (c2 << 8) | c3;
    g_merge[i] = key;
    atomicOr(&g_w[key >> 5].x, 1u << (key & 31));
    *(float4*)&out[O9 + 4LL * i] = make_float4((float)c0, (float)c1, (float)c2, (float)c3);
}

__device__ __forceinline__ int blockScanExcl256(int v, int* shw, int& total) {
    int lane = threadIdx.x & 31, w = threadIdx.x >> 5;
    int x = v;
    #pragma unroll
    for (int o = 1; o < 32; o <<= 1) { int y = __shfl_up_sync(~0u, x, o); if (lane >= o) x += y; }
    if (lane == 31) shw[w] = x;
    __syncthreads();
    if (threadIdx.x < 8) {
        int s = shw[threadIdx.x];
        #pragma unroll
        for (int o = 1; o < 8; o <<= 1) { int y = __shfl_up_sync(0xFFu, s, o); if ((int)threadIdx.x >= o) s += y; }
        shw[threadIdx.x] = s;
    }
    __syncthreads();
    int excl = (w ? shw[w - 1] : 0) + x - v;
    total = shw[7];
    __syncthreads();
    return excl;
}

__global__ void k_bits_partial() {
    __shared__ int shw[8];
    int base = blockIdx.x * WPB;
    int s = 0;
    for (int it = 0; it < WPB / 256; it++) {
        int idx = base + it * 256 + threadIdx.x;
        if (idx < NWRD) s += __popc(g_w[idx].x);
    }
    #pragma unroll
    for (int o = 16; o; o >>= 1) s += __shfl_down_sync(~0u, s, o);
    if ((threadIdx.x & 31) == 0) shw[threadIdx.x >> 5] = s;
    __syncthreads();
    if (threadIdx.x == 0) {
        int t = 0;
        for (int k = 0; k < 8; k++) t += shw[k];
        g_bsums[blockIdx.x] = t;
    }
}

__global__ void k_scan_bsums(int nb) {
    __shared__ int sh[32];
    int t = threadIdx.x, lane = t & 31, w = t >> 5;
    int c = (nb + 1023) / 1024;
    int loc[16];
    int s = 0;
    for (int j = 0; j < c; j++) {
        int idx = t * c + j;
        int v = (idx < nb) ? g_bsums[idx] : 0;
        loc[j] = s; s += v;
    }
    int x = s;
    #pragma unroll
    for (int o = 1; o < 32; o <<= 1) { int y = __shfl_up_sync(~0u, x, o); if (lane >= o) x += y; }
    if (lane == 31) sh[w] = x;
    __syncthreads();
    if (t < 32) {
        int v2 = sh[t];
        #pragma unroll
        for (int o = 1; o < 32; o <<= 1) { int y = __shfl_up_sync(~0u, v2, o); if (t >= o) v2 += y; }
        sh[t] = v2;
    }
    __syncthreads();
    int excl = (w ? sh[w - 1] : 0) + x - s;
    for (int j = 0; j < c; j++) {
        int idx = t * c + j;
        if (idx < nb) g_bsums[idx] = excl + loc[j];
    }
}

// coalesced per-word rank prefix
__global__ void k_bits_final() {
    __shared__ int shw[8];
    int start = blockIdx.x * WPB;
    int base = g_bsums[blockIdx.x];
    for (int it = 0; it < WPB / 256; it++) {
        int idx = start + it * 256 + threadIdx.x;
        int pc = (idx < NWRD) ? __popc(g_w[idx].x) : 0;
        int tot;
        int excl = blockScanExcl256(pc, shw, tot);
        if (idx < NWRD) g_w[idx].y = (unsigned)(base + excl);
        base += tot;
    }
}

// thread per point: rank via popc, voxel_index output, count, cellof
__global__ void k_count(float* __restrict__ out, long long V, int n) {
    int i = blockIdx.x * blockDim.x + threadIdx.x;
    if (i >= n) return;
    int key = g_merge[i];
    uint2 wv = g_w[key >> 5];
    int r = (int)wv.y + __popc(wv.x & ((1u << (key & 31)) - 1u));
    g_merge[i] = r;
    g_cellof[r] = key;                 // same-value race: benign
    out[52LL * V + i] = (float)r;
    atomicAdd(&g_vcount[r], 1);
}

__global__ void k_vcount_partial(int nV) {
    __shared__ int shw[8];
    int base = blockIdx.x * CPB;
    int s = 0;
    for (int it = 0; it < CPB / 256; it++) {
        int idx = base + it * 256 + threadIdx.x;
        if (idx < nV) s += g_vcount[idx];
    }
    #pragma unroll
    for (int o = 16; o; o >>= 1) s += __shfl_down_sync(~0u, s, o);
    if ((threadIdx.x & 31) == 0) shw[threadIdx.x >> 5] = s;
    __syncthreads();
    if (threadIdx.x == 0) {
        int t = 0;
        for (int k = 0; k < 8; k++) t += shw[k];
        g_bsums[blockIdx.x] = t;
    }
}

// fused: voffset scan + multi-voxel accumulator zeroing + multi list
__global__ void k_vcount_final(float* __restrict__ out, long long V, int nV) {
    __shared__ int shw[8];
    int start = blockIdx.x * CPB;
    int base = g_bsums[blockIdx.x];
    for (int it = 0; it < CPB / 256; it++) {
        int idx = start + it * 256 + threadIdx.x;
        int v = (idx < nV) ? g_vcount[idx] : 0;
        int tot;
        int excl = blockScanExcl256(v, shw, tot);
        if (idx < nV) {
            g_voffset[idx] = base + excl;
            if (v > 1) {
                long long r = idx;
                *(float4*)&out[15LL * V + r * 4] = make_float4(0.f, 0.f, 0.f, 0.f);
                float4 z = make_float4(0.f, 0.f, 0.f, 0.f);
                float4* fp = (float4*)&out[19LL * V + r * 32];
                #pragma unroll
                for (int k = 0; k < 8; k++) fp[k] = z;
                g_cursor[idx] = 0;
                g_multilist[atomicAdd(&g_nmulti, 1)] = idx;
            }
        }
        base += tot;
    }
}

// warp per point: feat + bxyz (plain store for count==1) + median key bin
__global__ void k_accum2(const float* __restrict__ bxyz, const float* __restrict__ feat,
                         const float* __restrict__ h, float* __restrict__ out,
                         long long V, int n) {
    int lane = threadIdx.x & 31;
    int i = (blockIdx.x * blockDim.x + threadIdx.x) >> 5;
    if (i >= n) return;
    int r = g_merge[i];
    int c = g_vcount[r];
    float f = __ldg(&feat[(long long)i * 32 + lane]);
    long long fo = 19LL * V + (long long)r * 32 + lane;
    if (c == 1) out[fo] = f;
    else atomicAdd(&out[fo], f);
    if (lane < 4) {
        float b = __ldg(&bxyz[(long long)i * 4 + lane]);
        long long bo = 15LL * V + (long long)r * 4 + lane;
        if (c == 1) out[bo] = b;
        else atomicAdd(&out[bo], b);
    }
    if (lane == 0) {
        float tv = __fadd_rn(__fsub_rn(__ldg(&h[i]), g_st.hmin), __fmul_rn((float)r, g_st.hmax));
        int pos = (c == 1) ? 0 : atomicAdd(&g_cursor[r], 1);
        g_keyA[g_voffset[r] + pos] = fenc(tv);
    }
}

// thread per voxel: coalesced scalar outputs (bitfield decode)
__global__ void k_voxfin_scalar(float* __restrict__ out, const float* __restrict__ vs, long long V) {
    long long r = (long long)blockIdx.x * blockDim.x + threadIdx.x;
    if (r >= V) return;
    float vs1 = __ldg(&vs[1]), vs2 = __ldg(&vs[2]), vs3 = __ldg(&vs[3]);
    float mn1 = __uint_as_float(g_st.pcmin_bits[1]);
    float mn2 = __uint_as_float(g_st.pcmin_bits[2]);
    float mn3 = __uint_as_float(g_st.pcmin_bits[3]);
    int c = g_vcount[r];
    float4 s = *(float4*)&out[15LL * V + r * 4];
    if (c > 1) {
        float fc = (float)c;
        s.x = __fdiv_rn(s.x, fc);
        s.y = __fdiv_rn(s.y, fc);
        s.z = __fdiv_rn(s.z, fc);
        s.w = __fdiv_rn(s.w, fc);
        *(float4*)&out[15LL * V + r * 4] = s;
    }
    int key = g_cellof[r];
    int c0 = (key >> 24) & 255, c1 = (key >> 16) & 255, c2 = (key >> 8) & 255, c3 = key & 255;
    out[r] = (float)(int)rintf(s.x);
    out[V + r * 3 + 0] = s.y;
    out[V + r * 3 + 1] = s.z;
    out[V + r * 3 + 2] = s.w;
    float t1 = __fadd_rn(__fmul_rn((float)c1, vs1), mn1);
    float t2 = __fadd_rn(__fmul_rn((float)c2, vs2), mn2);
    float t3 = __fadd_rn(__fmul_rn((float)c3, vs3), mn3);
    float ctr1 = __fadd_rn(t1, __fdiv_rn(vs1, 2.0f));
    float ctr2 = __fadd_rn(t2, __fdiv_rn(vs2, 2.0f));
    float ctr3 = __fadd_rn(t3, __fdiv_rn(vs3, 2.0f));
    out[4LL * V + r * 3 + 0] = ctr1;
    out[4LL * V + r * 3 + 1] = ctr2;
    out[4LL * V + r * 3 + 2] = ctr3;
    *(float4*)&out[7LL * V + r * 4] = make_float4(s.x, ctr1, ctr2, ctr3);
    *(float4*)&out[11LL * V + r * 4] = make_float4((float)c0, (float)c1, (float)c2, (float)c3);
}

// warp per multi-voxel (compacted list): feat divide
__global__ void k_voxfin_feat(float* __restrict__ out, long long V) {
    int lane = threadIdx.x & 31;
    int w = (blockIdx.x * blockDim.x + threadIdx.x) >> 5;
    int nw = (gridDim.x * blockDim.x) >> 5;
    int nm = g_nmulti;
    for (int j = w; j < nm; j += nw) {
        long long r = g_multilist[j];
        float fc = (float)g_vcount[r];
        long long o = 19LL * V + r * 32 + lane;
        out[o] = __fdiv_rn(out[o], fc);
    }
}

// windowed exact selection over the (virtual) global sort — unchanged (passed 2x)
__global__ void k_median(float* __restrict__ out, long long V, int N) {
    long long r = (long long)blockIdx.x * blockDim.x + threadIdx.x;
    if (r >= V) return;
    float mx = g_st.hmax;
    int W = g_st.wwin;
    long long lo = r - W; if (lo < 0) lo = 0;
    long long hi = r + W; if (hi > V - 1) hi = V - 1;
    int s0 = g_voffset[lo];
    int sr = g_voffset[r];
    int s1 = (hi + 1 < V) ? g_voffset[hi + 1] : N;
    unsigned thr = fenc(__fmul_rn((float)r, mx));
    int p = sr + (g_vcount[r] >> 1);
    int low = s0;
    for (int j = s0; j < sr; j++)
        if (__ldg(&g_keyA[j]) < thr) low++;
    int kk = p - low;
    unsigned ans = 0u;
    for (int i = s0; i < s1; i++) {
        unsigned ki = __ldg(&g_keyA[i]);
        if (ki < thr) continue;
        int rank = 0;
        for (int j = s0; j < s1; j++) {
            unsigned kj = __ldg(&g_keyA[j]);
            if (kj < thr) continue;
            rank += (kj < ki) || (kj == ki && j < i);
        }
        if (rank == kk) { ans = ki; break; }
    }
    out[51LL * V + r] = __fsub_rn(fdec(ans), __fmul_rn((float)r, mx));
}

extern "C" void kernel_launch(void* const* d_in, const int* in_sizes, int n_in,
                              void* d_out, int out_size) {
    const float* bxyz = (const float*)d_in[0];
    const float* feat = (const float*)d_in[1];
    const float* hh = (const float*)d_in[2];
    const float* vs = (const float*)d_in[3];
    int N = in_sizes[0] / 4;
    long long V = ((long long)out_size - 5LL * N) / 52LL;
    float* out = (float*)d_out;

    void *p_w = 0, *p_vcount = 0;
    cudaGetSymbolAddress(&p_w, g_w);
    cudaGetSymbolAddress(&p_vcount, g_vcount);

    int NBW = (NWRD + WPB - 1) / WPB;
    int NBV = (int)((V + CPB - 1) / CPB);
    int BPT = (N + 255) / 256;
    int BWP = (int)(((long long)N * 32 + 255) / 256);
    int BVT = (int)((V + 255) / 256);

    cudaMemsetAsync(p_w, 0, sizeof(uint2) * NWRD);
    cudaMemsetAsync(p_vcount, 0, sizeof(int) * (size_t)V);

    k_init<<<1, 32>>>();
    k_stats<<<2048, 256>>>((const float4*)bxyz, hh, N);
    k_small<<<1, 1>>>();
    k_merge<<<BPT, 256>>>((const float4*)bxyz, vs, out, V, N);
    k_bits_partial<<<NBW, 256>>>();
    k_scan_bsums<<<1, 1024>>>(NBW);
    k_bits_final<<<NBW, 256>>>();
    k_count<<<BPT, 256>>>(out, V, N);
    k_vcount_partial<<<NBV, 256>>>((int)V);
    k_scan_bsums<<<1, 1024>>>(NBV);
    k_vcount_final<<<NBV, 256>>>(out, V, (int)V);
    k_accum2<<<BWP, 256>>>(bxyz, feat, hh, out, V, N);
    k_voxfin_scalar<<<BVT, 256>>>(out, vs, V);
    k_voxfin_feat<<<2048, 256>>>(out, V);
    k_median<<<BVT, 256>>>(out, V, N);
}

// round 8
// speedup vs baseline: 2.3879x; 1.0211x over previous
#include <cuda_runtime.h>

#define NMAX 2000128
#define NKEY (1 << 26)
#define NWRD (NKEY / 32)
#define WPB 8192
#define CPB 8192

__device__ uint2 g_w[NWRD];             // {occupancy mask, exclusive rank prefix}
__device__ int g_merge[NMAX];           // bitfield key per point
__device__ unsigned g_keyA[NMAX];       // encoded tvals binned by voxel
__device__ int g_vcount[NMAX];
__device__ int g_voffset[NMAX];
__device__ int g_cellof[NMAX];          // rank -> bitfield key
__device__ int g_cursor[NMAX];
__device__ int g_bsums[8448];
__device__ int g_multilist[NMAX];
__device__ int g_nmulti;

struct Stats {
    unsigned pcmin_bits[4];
    unsigned hmin_e, hmax_e;
    float hmin, hmax;
    int wwin;
};
__device__ Stats g_st;

__device__ __forceinline__ unsigned fenc(float f) {
    unsigned b = __float_as_uint(f);
    return (b & 0x80000000u) ? ~b : (b | 0x80000000u);
}
__device__ __forceinline__ float fdec(unsigned u) {
    return __uint_as_float((u & 0x80000000u) ? (u ^ 0x80000000u) : ~u);
}

__global__ void k_init() {
    int t = threadIdx.x;
    if (t < 4) g_st.pcmin_bits[t] = 0x7F800000u;
    if (t == 4) { g_st.hmin_e = 0xFFFFFFFFu; g_st.hmax_e = 0u; g_nmulti = 0; }
}

// flat: thread handles 4 consecutive points (5 independent wide loads)
__global__ void k_stats(const float4* __restrict__ bxyz, const float4* __restrict__ h4,
                        const float* __restrict__ h, int n) {
    int t = blockIdx.x * blockDim.x + threadIdx.x;
    int base = t * 4;
    float m0 = 3.4e38f, m1 = 3.4e38f, m2 = 3.4e38f, m3 = 3.4e38f;
    unsigned he0 = 0xFFFFFFFFu, he1 = 0u;
    if (base + 3 < n) {
        float4 p0 = __ldg(&bxyz[base]);
        float4 p1 = __ldg(&bxyz[base + 1]);
        float4 p2 = __ldg(&bxyz[base + 2]);
        float4 p3 = __ldg(&bxyz[base + 3]);
        float4 hv = __ldg(&h4[t]);
        m0 = fminf(fminf(p0.x, p1.x), fminf(p2.x, p3.x));
        m1 = fminf(fminf(p0.y, p1.y), fminf(p2.y, p3.y));
        m2 = fminf(fminf(p0.z, p1.z), fminf(p2.z, p3.z));
        m3 = fminf(fminf(p0.w, p1.w), fminf(p2.w, p3.w));
        unsigned e0 = fenc(hv.x), e1 = fenc(hv.y), e2 = fenc(hv.z), e3 = fenc(hv.w);
        he0 = min(min(e0, e1), min(e2, e3));
        he1 = max(max(e0, e1), max(e2, e3));
    } else {
        for (int i = base; i < n; i++) {
            float4 p = __ldg(&bxyz[i]);
            m0 = fminf(m0, p.x); m1 = fminf(m1, p.y);
            m2 = fminf(m2, p.z); m3 = fminf(m3, p.w);
            unsigned e = fenc(__ldg(&h[i]));
            he0 = min(he0, e); he1 = max(he1, e);
        }
    }
    #pragma unroll
    for (int o = 16; o; o >>= 1) {
        m0 = fminf(m0, __shfl_down_sync(~0u, m0, o));
        m1 = fminf(m1, __shfl_down_sync(~0u, m1, o));
        m2 = fminf(m2, __shfl_down_sync(~0u, m2, o));
        m3 = fminf(m3, __shfl_down_sync(~0u, m3, o));
        he0 = min(he0, __shfl_down_sync(~0u, he0, o));
        he1 = max(he1, __shfl_down_sync(~0u, he1, o));
    }
    if ((threadIdx.x & 31) == 0) {
        atomicMin(&g_st.pcmin_bits[0], __float_as_uint(m0));
        atomicMin(&g_st.pcmin_bits[1], __float_as_uint(m1));
        atomicMin(&g_st.pcmin_bits[2], __float_as_uint(m2));
        atomicMin(&g_st.pcmin_bits[3], __float_as_uint(m3));
        atomicMin(&g_st.hmin_e, he0);
        atomicMax(&g_st.hmax_e, he1);
    }
}

__global__ void k_small() {
    float mn = fdec(g_st.hmin_e), mx = fdec(g_st.hmax_e);
    g_st.hmin = mn;
    g_st.hmax = mx;
    int w = 64;
    if (mx > 0.0f) {
        float ratio = (mx - mn) / mx;
        if (ratio < 60.0f) w = (int)ratio + 2;
    }
    g_st.wwin = w;
}

__global__ void k_merge(const float4* __restrict__ bxyz, const float* __restrict__ vs,
                        float* __restrict__ out, long long V, int n) {
    float mn0 = __uint_as_float(g_st.pcmin_bits[0]);
    float mn1 = __uint_as_float(g_st.pcmin_bits[1]);
    float mn2 = __uint_as_float(g_st.pcmin_bits[2]);
    float mn3 = __uint_as_float(g_st.pcmin_bits[3]);
    float v0 = __ldg(&vs[0]), v1 = __ldg(&vs[1]), v2 = __ldg(&vs[2]), v3 = __ldg(&vs[3]);
    long long O9 = 52LL * V + n;
    int i = blockIdx.x * blockDim.x + threadIdx.x;
    if (i >= n) return;
    float4 p = __ldg(&bxyz[i]);
    int c0 = (int)floorf(__fdiv_rn(__fsub_rn(p.x, mn0), v0));
    int c1 = (int)floorf(__fdiv_rn(__fsub_rn(p.y, mn1), v1));
    int c2 = (int)floorf(__fdiv_rn(__fsub_rn(p.z, mn2), v2));
    int c3 = (int)floorf(__fdiv_rn(__fsub_rn(p.w, mn3), v3));
    int key = (c0 << 24) | (c1 << 16) | (c2 << 8) | c3;
    g_merge[i] = key;
    atomicOr(&g_w[key >> 5].x, 1u << (key & 31));
    *(float4*)&out[O9 + 4LL * i] = make_float4((float)c0, (float)c1, (float)c2, (float)c3);
}

__device__ __forceinline__ int blockScanExcl256(int v, int* shw, int& total) {
    int lane = threadIdx.x & 31, w = threadIdx.x >> 5;
    int x = v;
    #pragma unroll
    for (int o = 1; o < 32; o <<= 1) { int y = __shfl_up_sync(~0u, x, o); if (lane >= o) x += y; }
    if (lane == 31) shw[w] = x;
    __syncthreads();
    if (threadIdx.x < 8) {
        int s = shw[threadIdx.x];
        #pragma unroll
        for (int o = 1; o < 8; o <<= 1) { int y = __shfl_up_sync(0xFFu, s, o); if ((int)threadIdx.x >= o) s += y; }
        shw[threadIdx.x] = s;
    }
    __syncthreads();
    int excl = (w ? shw[w - 1] : 0) + x - v;
    total = shw[7];
    __syncthreads();
    return excl;
}

__global__ void k_bits_partial() {
    __shared__ int shw[8];
    int base = blockIdx.x * WPB;
    int s = 0;
    for (int it = 0; it < WPB / 256; it++) {
        int idx = base + it * 256 + threadIdx.x;
        if (idx < NWRD) s += __popc(g_w[idx].x);
    }
    #pragma unroll
    for (int o = 16; o; o >>= 1) s += __shfl_down_sync(~0u, s, o);
    if ((threadIdx.x & 31) == 0) shw[threadIdx.x >> 5] = s;
    __syncthreads();
    if (threadIdx.x == 0) {
        int t = 0;
        for (int k = 0; k < 8; k++) t += shw[k];
        g_bsums[blockIdx.x] = t;
    }
}

__global__ void k_scan_bsums(int nb) {
    __shared__ int sh[32];
    int t = threadIdx.x, lane = t & 31, w = t >> 5;
    int c = (nb + 1023) / 1024;
    int loc[16];
    int s = 0;
    for (int j = 0; j < c; j++) {
        int idx = t * c + j;
        int v = (idx < nb) ? g_bsums[idx] : 0;
        loc[j] = s; s += v;
    }
    int x = s;
    #pragma unroll
    for (int o = 1; o < 32; o <<= 1) { int y = __shfl_up_sync(~0u, x, o); if (lane >= o) x += y; }
    if (lane == 31) sh[w] = x;
    __syncthreads();
    if (t < 32) {
        int v2 = sh[t];
        #pragma unroll
        for (int o = 1; o < 32; o <<= 1) { int y = __shfl_up_sync(~0u, v2, o); if (t >= o) v2 += y; }
        sh[t] = v2;
    }
    __syncthreads();
    int excl = (w ? sh[w - 1] : 0) + x - s;
    for (int j = 0; j < c; j++) {
        int idx = t * c + j;
        if (idx < nb) g_bsums[idx] = excl + loc[j];
    }
}

__global__ void k_bits_final() {
    __shared__ int shw[8];
    int start = blockIdx.x * WPB;
    int base = g_bsums[blockIdx.x];
    for (int it = 0; it < WPB / 256; it++) {
        int idx = start + it * 256 + threadIdx.x;
        int pc = (idx < NWRD) ? __popc(g_w[idx].x) : 0;
        int tot;
        int excl = blockScanExcl256(pc, shw, tot);
        if (idx < NWRD) g_w[idx].y = (unsigned)(base + excl);
        base += tot;
    }
}

__global__ void k_count(float* __restrict__ out, long long V, int n) {
    int i = blockIdx.x * blockDim.x + threadIdx.x;
    if (i >= n) return;
    int key = g_merge[i];
    uint2 wv = g_w[key >> 5];
    int r = (int)wv.y + __popc(wv.x & ((1u << (key & 31)) - 1u));
    g_cellof[r] = key;                 // same-value race: benign
    out[52LL * V + i] = (float)r;
    atomicAdd(&g_vcount[r], 1);
}

__global__ void k_vcount_partial(int nV) {
    __shared__ int shw[8];
    int base = blockIdx.x * CPB;
    int s = 0;
    for (int it = 0; it < CPB / 256; it++) {
        int idx = base + it * 256 + threadIdx.x;
        if (idx < nV) s += g_vcount[idx];
    }
    #pragma unroll
    for (int o = 16; o; o >>= 1) s += __shfl_down_sync(~0u, s, o);
    if ((threadIdx.x & 31) == 0) shw[threadIdx.x >> 5] = s;
    __syncthreads();
    if (threadIdx.x == 0) {
        int t = 0;
        for (int k = 0; k < 8; k++) t += shw[k];
        g_bsums[blockIdx.x] = t;
    }
}

__global__ void k_vcount_final(float* __restrict__ out, long long V, int nV) {
    __shared__ int shw[8];
    int start = blockIdx.x * CPB;
    int base = g_bsums[blockIdx.x];
    for (int it = 0; it < CPB / 256; it++) {
        int idx = start + it * 256 + threadIdx.x;
        int v = (idx < nV) ? g_vcount[idx] : 0;
        int tot;
        int excl = blockScanExcl256(v, shw, tot);
        if (idx < nV) {
            g_voffset[idx] = base + excl;
            if (v > 1) {
                long long r = idx;
                *(float4*)&out[15LL * V + r * 4] = make_float4(0.f, 0.f, 0.f, 0.f);
                float4 z = make_float4(0.f, 0.f, 0.f, 0.f);
                float4* fp = (float4*)&out[19LL * V + r * 32];
                #pragma unroll
                for (int k = 0; k < 8; k++) fp[k] = z;
                g_cursor[idx] = 0;
                g_multilist[atomicAdd(&g_nmulti, 1)] = idx;
            }
        }
        base += tot;
    }
}

__device__ __forceinline__ void accum_point(int i, int lane,
                                            const float* __restrict__ bxyz,
                                            const float* __restrict__ feat,
                                            const float* __restrict__ h,
                                            float* __restrict__ out, long long V) {
    int key = g_merge[i];
    uint2 wv = g_w[key >> 5];
    int r = (int)wv.y + __popc(wv.x & ((1u << (key & 31)) - 1u));
    int c = g_vcount[r];
    float f = __ldg(&feat[(long long)i * 32 + lane]);
    long long fo = 19LL * V + (long long)r * 32 + lane;
    if (c == 1) __stcs(&out[fo], f);
    else atomicAdd(&out[fo], f);
    if (lane < 4) {
        float b = __ldg(&bxyz[(long long)i * 4 + lane]);
        long long bo = 15LL * V + (long long)r * 4 + lane;
        if (c == 1) out[bo] = b;
        else atomicAdd(&out[bo], b);
    }
    if (lane == 0) {
        float tv = __fadd_rn(__fsub_rn(__ldg(&h[i]), g_st.hmin), __fmul_rn((float)r, g_st.hmax));
        int pos = (c == 1) ? 0 : atomicAdd(&g_cursor[r], 1);
        g_keyA[g_voffset[r] + pos] = fenc(tv);
    }
}

// warp handles 2 consecutive points (2 independent chains)
__global__ void k_accum2(const float* __restrict__ bxyz, const float* __restrict__ feat,
                         const float* __restrict__ h, float* __restrict__ out,
                         long long V, int n) {
    int lane = threadIdx.x & 31;
    int w = (blockIdx.x * blockDim.x + threadIdx.x) >> 5;
    int i0 = w * 2;
    if (i0 >= n) return;
    accum_point(i0, lane, bxyz, feat, h, out, V);
    if (i0 + 1 < n) accum_point(i0 + 1, lane, bxyz, feat, h, out, V);
}

// warp per multi-voxel: feat divide
__global__ void k_voxfin_feat(float* __restrict__ out, long long V) {
    int lane = threadIdx.x & 31;
    int w = (blockIdx.x * blockDim.x + threadIdx.x) >> 5;
    int nw = (gridDim.x * blockDim.x) >> 5;
    int nm = g_nmulti;
    for (int j = w; j < nm; j += nw) {
        long long r = g_multilist[j];
        float fc = (float)g_vcount[r];
        long long o = 19LL * V + r * 32 + lane;
        out[o] = __fdiv_rn(out[o], fc);
    }
}

// fused: per-voxel scalar outputs + windowed-global-sort median
__global__ void k_final(float* __restrict__ out, const float* __restrict__ vs,
                        long long V, int N) {
    long long r = (long long)blockIdx.x * blockDim.x + threadIdx.x;
    if (r >= V) return;
    float vs1 = __ldg(&vs[1]), vs2 = __ldg(&vs[2]), vs3 = __ldg(&vs[3]);
    float mn1 = __uint_as_float(g_st.pcmin_bits[1]);
    float mn2 = __uint_as_float(g_st.pcmin_bits[2]);
    float mn3 = __uint_as_float(g_st.pcmin_bits[3]);
    int c = g_vcount[r];
    float4 s = *(float4*)&out[15LL * V + r * 4];
    if (c > 1) {
        float fc = (float)c;
        s.x = __fdiv_rn(s.x, fc);
        s.y = __fdiv_rn(s.y, fc);
        s.z = __fdiv_rn(s.z, fc);
        s.w = __fdiv_rn(s.w, fc);
        *(float4*)&out[15LL * V + r * 4] = s;
    }
    int key = g_cellof[r];
    int c0 = (key >> 24) & 255, c1 = (key >> 16) & 255, c2 = (key >> 8) & 255, c3 = key & 255;
    out[r] = (float)(int)rintf(s.x);
    out[V + r * 3 + 0] = s.y;
    out[V + r * 3 + 1] = s.z;
    out[V + r * 3 + 2] = s.w;
    float t1 = __fadd_rn(__fmul_rn((float)c1, vs1), mn1);
    float t2 = __fadd_rn(__fmul_rn((float)c2, vs2), mn2);
    float t3 = __fadd_rn(__fmul_rn((float)c3, vs3), mn3);
    float ctr1 = __fadd_rn(t1, __fdiv_rn(vs1, 2.0f));
    float ctr2 = __fadd_rn(t2, __fdiv_rn(vs2, 2.0f));
    float ctr3 = __fadd_rn(t3, __fdiv_rn(vs3, 2.0f));
    out[4LL * V + r * 3 + 0] = ctr1;
    out[4LL * V + r * 3 + 1] = ctr2;
    out[4LL * V + r * 3 + 2] = ctr3;
    *(float4*)&out[7LL * V + r * 4] = make_float4(s.x, ctr1, ctr2, ctr3);
    *(float4*)&out[11LL * V + r * 4] = make_float4((float)c0, (float)c1, (float)c2, (float)c3);

    // median (windowed exact selection over the virtual global sort)
    float mx = g_st.hmax;
    int W = g_st.wwin;
    long long lo = r - W; if (lo < 0) lo = 0;
    long long hi = r + W; if (hi > V - 1) hi = V - 1;
    int s0 = g_voffset[lo];
    int sr = g_voffset[r];
    int s1 = (hi + 1 < V) ? g_voffset[hi + 1] : N;
    unsigned thr = fenc(__fmul_rn((float)r, mx));
    int p = sr + (c >> 1);
    int low = s0;
    for (int j = s0; j < sr; j++)
        if (__ldg(&g_keyA[j]) < thr) low++;
    int kk = p - low;
    unsigned ans = 0u;
    for (int i = s0; i < s1; i++) {
        unsigned ki = __ldg(&g_keyA[i]);
        if (ki < thr) continue;
        int rank = 0;
        for (int j = s0; j < s1; j++) {
            unsigned kj = __ldg(&g_keyA[j]);
            if (kj < thr) continue;
            rank += (kj < ki) || (kj == ki && j < i);
        }
        if (rank == kk) { ans = ki; break; }
    }
    out[51LL * V + r] = __fsub_rn(fdec(ans), __fmul_rn((float)r, mx));
}

extern "C" void kernel_launch(void* const* d_in, const int* in_sizes, int n_in,
                              void* d_out, int out_size) {
    const float* bxyz = (const float*)d_in[0];
    const float* feat = (const float*)d_in[1];
    const float* hh = (const float*)d_in[2];
    const float* vs = (const float*)d_in[3];
    int N = in_sizes[0] / 4;
    long long V = ((long long)out_size - 5LL * N) / 52LL;
    float* out = (float*)d_out;

    void *p_w = 0, *p_vcount = 0;
    cudaGetSymbolAddress(&p_w, g_w);
    cudaGetSymbolAddress(&p_vcount, g_vcount);

    int NBW = (NWRD + WPB - 1) / WPB;
    int NBV = (int)((V + CPB - 1) / CPB);
    int BPT = (N + 255) / 256;
    int BS4 = ((N + 3) / 4 + 255) / 256;
    int BW2 = (int)((((long long)(N + 1) / 2) * 32 + 255) / 256);
    int BVT = (int)((V + 255) / 256);

    cudaMemsetAsync(p_w, 0, sizeof(uint2) * NWRD);
    cudaMemsetAsync(p_vcount, 0, sizeof(int) * (size_t)V);

    k_init<<<1, 32>>>();
    k_stats<<<BS4, 256>>>((const float4*)bxyz, (const float4*)hh, hh, N);
    k_small<<<1, 1>>>();
    k_merge<<<BPT, 256>>>((const float4*)bxyz, vs, out, V, N);
    k_bits_partial<<<NBW, 256>>>();
    k_scan_bsums<<<1, 1024>>>(NBW);
    k_bits_final<<<NBW, 256>>>();
    k_count<<<BPT, 256>>>(out, V, N);
    k_vcount_partial<<<NBV, 256>>>((int)V);
    k_scan_bsums<<<1, 1024>>>(NBV);
    k_vcount_final<<<NBV, 256>>>(out, V, (int)V);
    k_accum2<<<BW2, 256>>>(bxyz, feat, hh, out, V, N);
    k_voxfin_feat<<<2048, 256>>>(out, V);
    k_final<<<BVT, 256>>>(out, vs, V, N);
}

// round 9
// speedup vs baseline: 2.4466x; 1.0246x over previous
#include <cuda_runtime.h>

#define NMAX 2000128
#define NKEY (1 << 26)
#define NWRD (NKEY / 32)
#define WPB 8192
#define CPB 8192

__device__ uint2 g_w[NWRD];             // {occupancy mask, exclusive rank prefix}
__device__ int g_merge[NMAX];           // bitfield key per point
__device__ unsigned g_keyA[NMAX];       // encoded tvals binned by voxel
__device__ int g_vcount[NMAX];
__device__ int g_voffset[NMAX];
__device__ int g_cellof[NMAX];          // rank -> bitfield key
__device__ int g_cursor[NMAX];
__device__ int g_bsums[8448];
__device__ int g_multilist[NMAX];
__device__ int g_nmulti;

struct Stats {
    unsigned pcmin_bits[4];
    unsigned hmin_e, hmax_e;
    float hmin, hmax;
    int wwin;
};
__device__ Stats g_st;

__device__ __forceinline__ unsigned fenc(float f) {
    unsigned b = __float_as_uint(f);
    return (b & 0x80000000u) ? ~b : (b | 0x80000000u);
}
__device__ __forceinline__ float fdec(unsigned u) {
    return __uint_as_float((u & 0x80000000u) ? (u ^ 0x80000000u) : ~u);
}

__global__ void k_init() {
    int t = threadIdx.x;
    if (t < 4) g_st.pcmin_bits[t] = 0x7F800000u;
    if (t == 4) { g_st.hmin_e = 0xFFFFFFFFu; g_st.hmax_e = 0u; g_nmulti = 0; }
}

__global__ void k_stats(const float4* __restrict__ bxyz, const float4* __restrict__ h4,
                        const float* __restrict__ h, int n) {
    int t = blockIdx.x * blockDim.x + threadIdx.x;
    int base = t * 4;
    float m0 = 3.4e38f, m1 = 3.4e38f, m2 = 3.4e38f, m3 = 3.4e38f;
    unsigned he0 = 0xFFFFFFFFu, he1 = 0u;
    if (base + 3 < n) {
        float4 p0 = __ldg(&bxyz[base]);
        float4 p1 = __ldg(&bxyz[base + 1]);
        float4 p2 = __ldg(&bxyz[base + 2]);
        float4 p3 = __ldg(&bxyz[base + 3]);
        float4 hv = __ldg(&h4[t]);
        m0 = fminf(fminf(p0.x, p1.x), fminf(p2.x, p3.x));
        m1 = fminf(fminf(p0.y, p1.y), fminf(p2.y, p3.y));
        m2 = fminf(fminf(p0.z, p1.z), fminf(p2.z, p3.z));
        m3 = fminf(fminf(p0.w, p1.w), fminf(p2.w, p3.w));
        unsigned e0 = fenc(hv.x), e1 = fenc(hv.y), e2 = fenc(hv.z), e3 = fenc(hv.w);
        he0 = min(min(e0, e1), min(e2, e3));
        he1 = max(max(e0, e1), max(e2, e3));
    } else {
        for (int i = base; i < n; i++) {
            float4 p = __ldg(&bxyz[i]);
            m0 = fminf(m0, p.x); m1 = fminf(m1, p.y);
            m2 = fminf(m2, p.z); m3 = fminf(m3, p.w);
            unsigned e = fenc(__ldg(&h[i]));
            he0 = min(he0, e); he1 = max(he1, e);
        }
    }
    #pragma unroll
    for (int o = 16; o; o >>= 1) {
        m0 = fminf(m0, __shfl_down_sync(~0u, m0, o));
        m1 = fminf(m1, __shfl_down_sync(~0u, m1, o));
        m2 = fminf(m2, __shfl_down_sync(~0u, m2, o));
        m3 = fminf(m3, __shfl_down_sync(~0u, m3, o));
        he0 = min(he0, __shfl_down_sync(~0u, he0, o));
        he1 = max(he1, __shfl_down_sync(~0u, he1, o));
    }
    if ((threadIdx.x & 31) == 0) {
        atomicMin(&g_st.pcmin_bits[0], __float_as_uint(m0));
        atomicMin(&g_st.pcmin_bits[1], __float_as_uint(m1));
        atomicMin(&g_st.pcmin_bits[2], __float_as_uint(m2));
        atomicMin(&g_st.pcmin_bits[3], __float_as_uint(m3));
        atomicMin(&g_st.hmin_e, he0);
        atomicMax(&g_st.hmax_e, he1);
    }
}

__global__ void k_merge(const float4* __restrict__ bxyz, const float* __restrict__ vs,
                        float* __restrict__ out, long long V, int n) {
    float mn0 = __uint_as_float(g_st.pcmin_bits[0]);
    float mn1 = __uint_as_float(g_st.pcmin_bits[1]);
    float mn2 = __uint_as_float(g_st.pcmin_bits[2]);
    float mn3 = __uint_as_float(g_st.pcmin_bits[3]);
    float v0 = __ldg(&vs[0]), v1 = __ldg(&vs[1]), v2 = __ldg(&vs[2]), v3 = __ldg(&vs[3]);
    long long O9 = 52LL * V + n;
    int i = blockIdx.x * blockDim.x + threadIdx.x;
    if (i >= n) return;
    float4 p = __ldg(&bxyz[i]);
    int c0 = (int)floorf(__fdiv_rn(__fsub_rn(p.x, mn0), v0));
    int c1 = (int)floorf(__fdiv_rn(__fsub_rn(p.y, mn1), v1));
    int c2 = (int)floorf(__fdiv_rn(__fsub_rn(p.z, mn2), v2));
    int c3 = (int)floorf(__fdiv_rn(__fsub_rn(p.w, mn3), v3));
    int key = (c0 << 24) | (c1 << 16) | (c2 << 8) | c3;
    g_merge[i] = key;
    atomicOr(&g_w[key >> 5].x, 1u << (key & 31));
    *(float4*)&out[O9 + 4LL * i] = make_float4((float)c0, (float)c1, (float)c2, (float)c3);
}

__device__ __forceinline__ int blockScanExcl256(int v, int* shw, int& total) {
    int lane = threadIdx.x & 31, w = threadIdx.x >> 5;
    int x = v;
    #pragma unroll
    for (int o = 1; o < 32; o <<= 1) { int y = __shfl_up_sync(~0u, x, o); if (lane >= o) x += y; }
    if (lane == 31) shw[w] = x;
    __syncthreads();
    if (threadIdx.x < 8) {
        int s = shw[threadIdx.x];
        #pragma unroll
        for (int o = 1; o < 8; o <<= 1) { int y = __shfl_up_sync(0xFFu, s, o); if ((int)threadIdx.x >= o) s += y; }
        shw[threadIdx.x] = s;
    }
    __syncthreads();
    int excl = (w ? shw[w - 1] : 0) + x - v;
    total = shw[7];
    __syncthreads();
    return excl;
}

// k_small folded in: block 0 thread 0 finalizes hmin/hmax/wwin
__global__ void k_bits_partial() {
    __shared__ int shw[8];
    if (blockIdx.x == 0 && threadIdx.x == 0) {
        float mn = fdec(g_st.hmin_e), mx = fdec(g_st.hmax_e);
        g_st.hmin = mn;
        g_st.hmax = mx;
        int w = 64;
        if (mx > 0.0f) {
            float ratio = (mx - mn) / mx;
            if (ratio < 60.0f) w = (int)ratio + 2;
        }
        g_st.wwin = w;
    }
    int base = blockIdx.x * WPB;
    int s = 0;
    for (int it = 0; it < WPB / 256; it++) {
        int idx = base + it * 256 + threadIdx.x;
        if (idx < NWRD) s += __popc(g_w[idx].x);
    }
    #pragma unroll
    for (int o = 16; o; o >>= 1) s += __shfl_down_sync(~0u, s, o);
    if ((threadIdx.x & 31) == 0) shw[threadIdx.x >> 5] = s;
    __syncthreads();
    if (threadIdx.x == 0) {
        int t = 0;
        for (int k = 0; k < 8; k++) t += shw[k];
        g_bsums[blockIdx.x] = t;
    }
}

__global__ void k_scan_bsums(int nb) {
    __shared__ int sh[32];
    int t = threadIdx.x, lane = t & 31, w = t >> 5;
    int c = (nb + 1023) / 1024;
    int loc[16];
    int s = 0;
    for (int j = 0; j < c; j++) {
        int idx = t * c + j;
        int v = (idx < nb) ? g_bsums[idx] : 0;
        loc[j] = s; s += v;
    }
    int x = s;
    #pragma unroll
    for (int o = 1; o < 32; o <<= 1) { int y = __shfl_up_sync(~0u, x, o); if (lane >= o) x += y; }
    if (lane == 31) sh[w] = x;
    __syncthreads();
    if (t < 32) {
        int v2 = sh[t];
        #pragma unroll
        for (int o = 1; o < 32; o <<= 1) { int y = __shfl_up_sync(~0u, v2, o); if (t >= o) v2 += y; }
        sh[t] = v2;
    }
    __syncthreads();
    int excl = (w ? sh[w - 1] : 0) + x - s;
    for (int j = 0; j < c; j++) {
        int idx = t * c + j;
        if (idx < nb) g_bsums[idx] = excl + loc[j];
    }
}

__global__ void k_bits_final() {
    __shared__ int shw[8];
    int start = blockIdx.x * WPB;
    int base = g_bsums[blockIdx.x];
    for (int it = 0; it < WPB / 256; it++) {
        int idx = start + it * 256 + threadIdx.x;
        int pc = (idx < NWRD) ? __popc(g_w[idx].x) : 0;
        int tot;
        int excl = blockScanExcl256(pc, shw, tot);
        if (idx < NWRD) g_w[idx].y = (unsigned)(base + excl);
        base += tot;
    }
}

__global__ void k_count(float* __restrict__ out, long long V, int n) {
    int i = blockIdx.x * blockDim.x + threadIdx.x;
    if (i >= n) return;
    int key = g_merge[i];
    uint2 wv = g_w[key >> 5];
    int r = (int)wv.y + __popc(wv.x & ((1u << (key & 31)) - 1u));
    __stcs(&g_cellof[r], key);         // same-value race: benign
    out[52LL * V + i] = (float)r;
    atomicAdd(&g_vcount[r], 1);
}

__global__ void k_vcount_partial(int nV) {
    __shared__ int shw[8];
    int base = blockIdx.x * CPB;
    int s = 0;
    for (int it = 0; it < CPB / 256; it++) {
        int idx = base + it * 256 + threadIdx.x;
        if (idx < nV) s += g_vcount[idx];
    }
    #pragma unroll
    for (int o = 16; o; o >>= 1) s += __shfl_down_sync(~0u, s, o);
    if ((threadIdx.x & 31) == 0) shw[threadIdx.x >> 5] = s;
    __syncthreads();
    if (threadIdx.x == 0) {
        int t = 0;
        for (int k = 0; k < 8; k++) t += shw[k];
        g_bsums[blockIdx.x] = t;
    }
}

__global__ void k_vcount_final(float* __restrict__ out, long long V, int nV) {
    __shared__ int shw[8];
    int start = blockIdx.x * CPB;
    int base = g_bsums[blockIdx.x];
    for (int it = 0; it < CPB / 256; it++) {
        int idx = start + it * 256 + threadIdx.x;
        int v = (idx < nV) ? g_vcount[idx] : 0;
        int tot;
        int excl = blockScanExcl256(v, shw, tot);
        if (idx < nV) {
            g_voffset[idx] = base + excl;
            if (v > 1) {
                long long r = idx;
                *(float4*)&out[15LL * V + r * 4] = make_float4(0.f, 0.f, 0.f, 0.f);
                float4 z = make_float4(0.f, 0.f, 0.f, 0.f);
                float4* fp = (float4*)&out[19LL * V + r * 32];
                #pragma unroll
                for (int k = 0; k < 8; k++) fp[k] = z;
                g_cursor[idx] = 0;
                g_multilist[atomicAdd(&g_nmulti, 1)] = idx;
            }
        }
        base += tot;
    }
}

__device__ __forceinline__ void accum_point(int i, int lane,
                                            const float* __restrict__ bxyz,
                                            const float* __restrict__ feat,
                                            const float* __restrict__ h,
                                            float* __restrict__ out, long long V) {
    int key = g_merge[i];
    uint2 wv = g_w[key >> 5];
    int r = (int)wv.y + __popc(wv.x & ((1u << (key & 31)) - 1u));
    int c = g_vcount[r];
    float f = __ldcs(&feat[(long long)i * 32 + lane]);
    long long fo = 19LL * V + (long long)r * 32 + lane;
    if (c == 1) __stcs(&out[fo], f);
    else atomicAdd(&out[fo], f);
    if (lane < 4) {
        float b = __ldg(&bxyz[(long long)i * 4 + lane]);
        long long bo = 15LL * V + (long long)r * 4 + lane;
        if (c == 1) out[bo] = b;
        else atomicAdd(&out[bo], b);
    }
    if (lane == 0) {
        float tv = __fadd_rn(__fsub_rn(__ldg(&h[i]), g_st.hmin), __fmul_rn((float)r, g_st.hmax));
        int pos = (c == 1) ? 0 : atomicAdd(&g_cursor[r], 1);
        g_keyA[g_voffset[r] + pos] = fenc(tv);
    }
}

__global__ void k_accum2(const float* __restrict__ bxyz, const float* __restrict__ feat,
                         const float* __restrict__ h, float* __restrict__ out,
                         long long V, int n) {
    int lane = threadIdx.x & 31;
    int w = (blockIdx.x * blockDim.x + threadIdx.x) >> 5;
    int i0 = w * 2;
    if (i0 >= n) return;
    accum_point(i0, lane, bxyz, feat, h, out, V);
    if (i0 + 1 < n) accum_point(i0 + 1, lane, bxyz, feat, h, out, V);
}

__global__ void k_voxfin_feat(float* __restrict__ out, long long V) {
    int lane = threadIdx.x & 31;
    int w = (blockIdx.x * blockDim.x + threadIdx.x) >> 5;
    int nw = (gridDim.x * blockDim.x) >> 5;
    int nm = g_nmulti;
    for (int j = w; j < nm; j += nw) {
        long long r = g_multilist[j];
        float fc = (float)g_vcount[r];
        long long o = 19LL * V + r * 32 + lane;
        out[o] = __fdiv_rn(out[o], fc);
    }
}

// fused: per-voxel scalar outputs + windowed-global-sort median (fast selection)
__global__ void k_final(float* __restrict__ out, const float* __restrict__ vs,
                        long long V, int N) {
    long long r = (long long)blockIdx.x * blockDim.x + threadIdx.x;
    if (r >= V) return;
    float vs1 = __ldg(&vs[1]), vs2 = __ldg(&vs[2]), vs3 = __ldg(&vs[3]);
    float mn1 = __uint_as_float(g_st.pcmin_bits[1]);
    float mn2 = __uint_as_float(g_st.pcmin_bits[2]);
    float mn3 = __uint_as_float(g_st.pcmin_bits[3]);
    int c = g_vcount[r];
    float4 s = *(float4*)&out[15LL * V + r * 4];
    if (c > 1) {
        float fc = (float)c;
        s.x = __fdiv_rn(s.x, fc);
        s.y = __fdiv_rn(s.y, fc);
        s.z = __fdiv_rn(s.z, fc);
        s.w = __fdiv_rn(s.w, fc);
        *(float4*)&out[15LL * V + r * 4] = s;
    }
    int key = g_cellof[r];
    int c0 = (key >> 24) & 255, c1 = (key >> 16) & 255, c2 = (key >> 8) & 255, c3 = key & 255;
    out[r] = (float)(int)rintf(s.x);
    out[V + r * 3 + 0] = s.y;
    out[V + r * 3 + 1] = s.z;
    out[V + r * 3 + 2] = s.w;
    float t1 = __fadd_rn(__fmul_rn((float)c1, vs1), mn1);
    float t2 = __fadd_rn(__fmul_rn((float)c2, vs2), mn2);
    float t3 = __fadd_rn(__fmul_rn((float)c3, vs3), mn3);
    float ctr1 = __fadd_rn(t1, __fdiv_rn(vs1, 2.0f));
    float ctr2 = __fadd_rn(t2, __fdiv_rn(vs2, 2.0f));
    float ctr3 = __fadd_rn(t3, __fdiv_rn(vs3, 2.0f));
    out[4LL * V + r * 3 + 0] = ctr1;
    out[4LL * V + r * 3 + 1] = ctr2;
    out[4LL * V + r * 3 + 2] = ctr3;
    *(float4*)&out[7LL * V + r * 4] = make_float4(s.x, ctr1, ctr2, ctr3);
    *(float4*)&out[11LL * V + r * 4] = make_float4((float)c0, (float)c1, (float)c2, (float)c3);

    // median: value at global-sort position voffset[r] + c/2, via windowed selection.
    // kk = (# keys >= thr in [s0,sr)) + c/2; then extract kk-th smallest >= thr
    // by iterative min-with-multiplicity (ties share the value, so index order
    // does not affect the returned value).
    float mx = g_st.hmax;
    int W = g_st.wwin;
    long long lo = r - W; if (lo < 0) lo = 0;
    long long hi = r + W; if (hi > V - 1) hi = V - 1;
    int s0 = g_voffset[lo];
    int sr = g_voffset[r];
    int s1 = (hi + 1 < V) ? g_voffset[hi + 1] : N;
    unsigned thr = fenc(__fmul_rn((float)r, mx));   // >= 0x80000000, so thr-1 safe
    int kk = c >> 1;
    for (int j = s0; j < sr; j++)
        if (__ldg(&g_keyA[j]) >= thr) kk++;
    unsigned last = thr - 1u;
    int remaining = kk + 1;
    unsigned ans = 0u;
    for (int guard = s1 - s0; guard > 0; guard--) {
        unsigned m = 0xFFFFFFFFu;
        int mult = 0;
        for (int j = s0; j < s1; j++) {
            unsigned k = __ldg(&g_keyA[j]);
            if (k > last) {
                if (k < m) { m = k; mult = 1; }
                else if (k == m) mult++;
            }
        }
        if (mult >= remaining) { ans = m; break; }
        remaining -= mult;
        last = m;
    }
    out[51LL * V + r] = __fsub_rn(fdec(ans), __fmul_rn((float)r, mx));
}

extern "C" void kernel_launch(void* const* d_in, const int* in_sizes, int n_in,
                              void* d_out, int out_size) {
    const float* bxyz = (const float*)d_in[0];
    const float* feat = (const float*)d_in[1];
    const float* hh = (const float*)d_in[2];
    const float* vs = (const float*)d_in[3];
    int N = in_sizes[0] / 4;
    long long V = ((long long)out_size - 5LL * N) / 52LL;
    float* out = (float*)d_out;

    void *p_w = 0, *p_vcount = 0;
    cudaGetSymbolAddress(&p_w, g_w);
    cudaGetSymbolAddress(&p_vcount, g_vcount);

    int NBW = (NWRD + WPB - 1) / WPB;
    int NBV = (int)((V + CPB - 1) / CPB);
    int BPT = (N + 255) / 256;
    int BS4 = ((N + 3) / 4 + 255) / 256;
    int BW2 = (int)((((long long)(N + 1) / 2) * 32 + 255) / 256);
    int BVT = (int)((V + 255) / 256);

    cudaMemsetAsync(p_w, 0, sizeof(uint2) * NWRD);
    cudaMemsetAsync(p_vcount, 0, sizeof(int) * (size_t)V);

    k_init<<<1, 32>>>();
    k_stats<<<BS4, 256>>>((const float4*)bxyz, (const float4*)hh, hh, N);
    k_merge<<<BPT, 256>>>((const float4*)bxyz, vs, out, V, N);
    k_bits_partial<<<NBW, 256>>>();
    k_scan_bsums<<<1, 1024>>>(NBW);
    k_bits_final<<<NBW, 256>>>();
    k_count<<<BPT, 256>>>(out, V, N);
    k_vcount_partial<<<NBV, 256>>>((int)V);
    k_scan_bsums<<<1, 1024>>>(NBV);
    k_vcount_final<<<NBV, 256>>>(out, V, (int)V);
    k_accum2<<<BW2, 256>>>(bxyz, feat, hh, out, V, N);
    k_voxfin_feat<<<2048, 256>>>(out, V);
    k_final<<<BVT, 256>>>(out, vs, V, N);
}

// round 10
// speedup vs baseline: 3.4494x; 1.4099x over previous
#include <cuda_runtime.h>

#define NMAX 2000128
#define NKEY (1 << 26)
#define NWRD (NKEY / 32)
#define WPB 8192
#define CPB 8192

__device__ uint2 g_w[NWRD];             // {occupancy mask, exclusive rank prefix}
__device__ int g_merge[NMAX];           // bitfield key per point
__device__ unsigned g_keyA[NMAX];       // encoded tvals binned by voxel
__device__ int g_vcount[NMAX];
__device__ int g_voffset[NMAX];
__device__ int g_cellof[NMAX];          // rank -> bitfield key
__device__ int g_cursor[NMAX];
__device__ int g_bsums[8448];
__device__ int g_multilist[NMAX];
__device__ int g_nmulti;

struct Stats {
    unsigned pcmin_bits[4];
    unsigned hmin_e, hmax_e;
    float hmin, hmax;
    int wwin;
};
__device__ Stats g_st;

__device__ __forceinline__ unsigned fenc(float f) {
    unsigned b = __float_as_uint(f);
    return (b & 0x80000000u) ? ~b : (b | 0x80000000u);
}
__device__ __forceinline__ float fdec(unsigned u) {
    return __uint_as_float((u & 0x80000000u) ? (u ^ 0x80000000u) : ~u);
}

__global__ void k_init() {
    int t = threadIdx.x;
    if (t < 4) g_st.pcmin_bits[t] = 0x7F800000u;
    if (t == 4) { g_st.hmin_e = 0xFFFFFFFFu; g_st.hmax_e = 0u; g_nmulti = 0; }
}

__global__ void k_stats(const float4* __restrict__ bxyz, const float4* __restrict__ h4,
                        const float* __restrict__ h, int n) {
    int t = blockIdx.x * blockDim.x + threadIdx.x;
    int base = t * 4;
    float m0 = 3.4e38f, m1 = 3.4e38f, m2 = 3.4e38f, m3 = 3.4e38f;
    unsigned he0 = 0xFFFFFFFFu, he1 = 0u;
    if (base + 3 < n) {
        float4 p0 = __ldg(&bxyz[base]);
        float4 p1 = __ldg(&bxyz[base + 1]);
        float4 p2 = __ldg(&bxyz[base + 2]);
        float4 p3 = __ldg(&bxyz[base + 3]);
        float4 hv = __ldg(&h4[t]);
        m0 = fminf(fminf(p0.x, p1.x), fminf(p2.x, p3.x));
        m1 = fminf(fminf(p0.y, p1.y), fminf(p2.y, p3.y));
        m2 = fminf(fminf(p0.z, p1.z), fminf(p2.z, p3.z));
        m3 = fminf(fminf(p0.w, p1.w), fminf(p2.w, p3.w));
        unsigned e0 = fenc(hv.x), e1 = fenc(hv.y), e2 = fenc(hv.z), e3 = fenc(hv.w);
        he0 = min(min(e0, e1), min(e2, e3));
        he1 = max(max(e0, e1), max(e2, e3));
    } else {
        for (int i = base; i < n; i++) {
            float4 p = __ldg(&bxyz[i]);
            m0 = fminf(m0, p.x); m1 = fminf(m1, p.y);
            m2 = fminf(m2, p.z); m3 = fminf(m3, p.w);
            unsigned e = fenc(__ldg(&h[i]));
            he0 = min(he0, e); he1 = max(he1, e);
        }
    }
    #pragma unroll
    for (int o = 16; o; o >>= 1) {
        m0 = fminf(m0, __shfl_down_sync(~0u, m0, o));
        m1 = fminf(m1, __shfl_down_sync(~0u, m1, o));
        m2 = fminf(m2, __shfl_down_sync(~0u, m2, o));
        m3 = fminf(m3, __shfl_down_sync(~0u, m3, o));
        he0 = min(he0, __shfl_down_sync(~0u, he0, o));
        he1 = max(he1, __shfl_down_sync(~0u, he1, o));
    }
    if ((threadIdx.x & 31) == 0) {
        atomicMin(&g_st.pcmin_bits[0], __float_as_uint(m0));
        atomicMin(&g_st.pcmin_bits[1], __float_as_uint(m1));
        atomicMin(&g_st.pcmin_bits[2], __float_as_uint(m2));
        atomicMin(&g_st.pcmin_bits[3], __float_as_uint(m3));
        atomicMin(&g_st.hmin_e, he0);
        atomicMax(&g_st.hmax_e, he1);
    }
}

__global__ void k_merge(const float4* __restrict__ bxyz, const float* __restrict__ vs,
                        float* __restrict__ out, long long V, int n) {
    float mn0 = __uint_as_float(g_st.pcmin_bits[0]);
    float mn1 = __uint_as_float(g_st.pcmin_bits[1]);
    float mn2 = __uint_as_float(g_st.pcmin_bits[2]);
    float mn3 = __uint_as_float(g_st.pcmin_bits[3]);
    float v0 = __ldg(&vs[0]), v1 = __ldg(&vs[1]), v2 = __ldg(&vs[2]), v3 = __ldg(&vs[3]);
    long long O9 = 52LL * V + n;
    int i = blockIdx.x * blockDim.x + threadIdx.x;
    if (i >= n) return;
    float4 p = __ldg(&bxyz[i]);
    int c0 = (int)floorf(__fdiv_rn(__fsub_rn(p.x, mn0), v0));
    int c1 = (int)floorf(__fdiv_rn(__fsub_rn(p.y, mn1), v1));
    int c2 = (int)floorf(__fdiv_rn(__fsub_rn(p.z, mn2), v2));
    int c3 = (int)floorf(__fdiv_rn(__fsub_rn(p.w, mn3), v3));
    int key = (c0 << 24) | (c1 << 16) | (c2 << 8) | c3;
    g_merge[i] = key;
    atomicOr(&g_w[key >> 5].x, 1u << (key & 31));
    *(float4*)&out[O9 + 4LL * i] = make_float4((float)c0, (float)c1, (float)c2, (float)c3);
}

__device__ __forceinline__ int blockScanExcl256(int v, int* shw, int& total) {
    int lane = threadIdx.x & 31, w = threadIdx.x >> 5;
    int x = v;
    #pragma unroll
    for (int o = 1; o < 32; o <<= 1) { int y = __shfl_up_sync(~0u, x, o); if (lane >= o) x += y; }
    if (lane == 31) shw[w] = x;
    __syncthreads();
    if (threadIdx.x < 8) {
        int s = shw[threadIdx.x];
        #pragma unroll
        for (int o = 1; o < 8; o <<= 1) { int y = __shfl_up_sync(0xFFu, s, o); if ((int)threadIdx.x >= o) s += y; }
        shw[threadIdx.x] = s;
    }
    __syncthreads();
    int excl = (w ? shw[w - 1] : 0) + x - v;
    total = shw[7];
    __syncthreads();
    return excl;
}

__global__ void k_bits_partial() {
    __shared__ int shw[8];
    if (blockIdx.x == 0 && threadIdx.x == 0) {
        float mn = fdec(g_st.hmin_e), mx = fdec(g_st.hmax_e);
        g_st.hmin = mn;
        g_st.hmax = mx;
        int w = 64;
        if (mx > 0.0f) {
            float ratio = (mx - mn) / mx;
            if (ratio < 60.0f) w = (int)ratio + 2;
        }
        g_st.wwin = w;
    }
    int base = blockIdx.x * WPB;
    int s = 0;
    for (int it = 0; it < WPB / 256; it++) {
        int idx = base + it * 256 + threadIdx.x;
        if (idx < NWRD) s += __popc(g_w[idx].x);
    }
    #pragma unroll
    for (int o = 16; o; o >>= 1) s += __shfl_down_sync(~0u, s, o);
    if ((threadIdx.x & 31) == 0) shw[threadIdx.x >> 5] = s;
    __syncthreads();
    if (threadIdx.x == 0) {
        int t = 0;
        for (int k = 0; k < 8; k++) t += shw[k];
        g_bsums[blockIdx.x] = t;
    }
}

__global__ void k_scan_bsums(int nb) {
    __shared__ int sh[32];
    int t = threadIdx.x, lane = t & 31, w = t >> 5;
    int c = (nb + 1023) / 1024;
    int loc[16];
    int s = 0;
    for (int j = 0; j < c; j++) {
        int idx = t * c + j;
        int v = (idx < nb) ? g_bsums[idx] : 0;
        loc[j] = s; s += v;
    }
    int x = s;
    #pragma unroll
    for (int o = 1; o < 32; o <<= 1) { int y = __shfl_up_sync(~0u, x, o); if (lane >= o) x += y; }
    if (lane == 31) sh[w] = x;
    __syncthreads();
    if (t < 32) {
        int v2 = sh[t];
        #pragma unroll
        for (int o = 1; o < 32; o <<= 1) { int y = __shfl_up_sync(~0u, v2, o); if (t >= o) v2 += y; }
        sh[t] = v2;
    }
    __syncthreads();
    int excl = (w ? sh[w - 1] : 0) + x - s;
    for (int j = 0; j < c; j++) {
        int idx = t * c + j;
        if (idx < nb) g_bsums[idx] = excl + loc[j];
    }
}

__global__ void k_bits_final() {
    __shared__ int shw[8];
    int start = blockIdx.x * WPB;
    int base = g_bsums[blockIdx.x];
    for (int it = 0; it < WPB / 256; it++) {
        int idx = start + it * 256 + threadIdx.x;
        int pc = (idx < NWRD) ? __popc(g_w[idx].x) : 0;
        int tot;
        int excl = blockScanExcl256(pc, shw, tot);
        if (idx < NWRD) g_w[idx].y = (unsigned)(base + excl);
        base += tot;
    }
}

__global__ void k_count(float* __restrict__ out, long long V, int n) {
    int i = blockIdx.x * blockDim.x + threadIdx.x;
    if (i >= n) return;
    int key = g_merge[i];
    uint2 wv = g_w[key >> 5];
    int r = (int)wv.y + __popc(wv.x & ((1u << (key & 31)) - 1u));
    __stcs(&g_cellof[r], key);         // same-value race: benign
    out[52LL * V + i] = (float)r;
    atomicAdd(&g_vcount[r], 1);
}

__global__ void k_vcount_partial(int nV) {
    __shared__ int shw[8];
    int base = blockIdx.x * CPB;
    int s = 0;
    for (int it = 0; it < CPB / 256; it++) {
        int idx = base + it * 256 + threadIdx.x;
        if (idx < nV) s += g_vcount[idx];
    }
    #pragma unroll
    for (int o = 16; o; o >>= 1) s += __shfl_down_sync(~0u, s, o);
    if ((threadIdx.x & 31) == 0) shw[threadIdx.x >> 5] = s;
    __syncthreads();
    if (threadIdx.x == 0) {
        int t = 0;
        for (int k = 0; k < 8; k++) t += shw[k];
        g_bsums[blockIdx.x] = t;
    }
}

__global__ void k_vcount_final(float* __restrict__ out, long long V, int nV) {
    __shared__ int shw[8];
    int start = blockIdx.x * CPB;
    int base = g_bsums[blockIdx.x];
    for (int it = 0; it < CPB / 256; it++) {
        int idx = start + it * 256 + threadIdx.x;
        int v = (idx < nV) ? g_vcount[idx] : 0;
        int tot;
        int excl = blockScanExcl256(v, shw, tot);
        if (idx < nV) {
            g_voffset[idx] = base + excl;
            if (v > 1) {
                long long r = idx;
                out[15LL * V + r * 4 + 0] = 0.f;
                out[15LL * V + r * 4 + 1] = 0.f;
                out[15LL * V + r * 4 + 2] = 0.f;
                out[15LL * V + r * 4 + 3] = 0.f;
                float* fp = &out[19LL * V + r * 32];
                #pragma unroll
                for (int k = 0; k < 32; k++) fp[k] = 0.f;
                g_cursor[idx] = 0;
                g_multilist[atomicAdd(&g_nmulti, 1)] = idx;
            }
        }
        base += tot;
    }
}

// warp = 4 points; 8 lanes x float4 per point. VEC=4 requires V%4==0 (vector
// stores into out at 19V+32r / 15V+4r are then 16B-aligned).
template <int VEC>
__global__ void k_accum2v(const float4* __restrict__ bxyz, const float4* __restrict__ feat4,
                          const float* __restrict__ h, float* __restrict__ out,
                          long long V, int n) {
    int gw = (blockIdx.x * blockDim.x + threadIdx.x) >> 5;
    int lane = threadIdx.x & 31;
    int sub = lane >> 3, comp = lane & 7;
    int i = gw * 4 + sub;
    if (i >= n) return;
    int key = g_merge[i];
    uint2 wv = g_w[key >> 5];
    int r = (int)wv.y + __popc(wv.x & ((1u << (key & 31)) - 1u));
    int c = g_vcount[r];
    float4 f = __ldcs(&feat4[(long long)i * 8 + comp]);
    long long fbase = 19LL * V + (long long)r * 32 + comp * 4;
    if (c == 1) {
        if (VEC == 4) {
            __stcs((float4*)&out[fbase], f);
        } else {
            __stcs(&out[fbase + 0], f.x);
            __stcs(&out[fbase + 1], f.y);
            __stcs(&out[fbase + 2], f.z);
            __stcs(&out[fbase + 3], f.w);
        }
    } else {
        atomicAdd(&out[fbase + 0], f.x);
        atomicAdd(&out[fbase + 1], f.y);
        atomicAdd(&out[fbase + 2], f.z);
        atomicAdd(&out[fbase + 3], f.w);
    }
    if (comp == 0) {
        float4 b = __ldg(&bxyz[i]);
        long long bo = 15LL * V + (long long)r * 4;
        if (c == 1) {
            if (VEC == 4) {
                *(float4*)&out[bo] = b;
            } else {
                out[bo + 0] = b.x; out[bo + 1] = b.y;
                out[bo + 2] = b.z; out[bo + 3] = b.w;
            }
        } else {
            atomicAdd(&out[bo + 0], b.x);
            atomicAdd(&out[bo + 1], b.y);
            atomicAdd(&out[bo + 2], b.z);
            atomicAdd(&out[bo + 3], b.w);
        }
    } else if (comp == 1) {
        float tv = __fadd_rn(__fsub_rn(__ldg(&h[i]), g_st.hmin), __fmul_rn((float)r, g_st.hmax));
        int pos = (c == 1) ? 0 : atomicAdd(&g_cursor[r], 1);
        g_keyA[g_voffset[r] + pos] = fenc(tv);
    }
}

// warp = 4 multi-voxels; 8 lanes x float4 RW (alignment per VEC)
template <int VEC>
__global__ void k_voxfin_feat(float* __restrict__ out, long long V) {
    int lane = threadIdx.x & 31;
    int gw = (blockIdx.x * blockDim.x + threadIdx.x) >> 5;
    int nw = (gridDim.x * blockDim.x) >> 5;
    int sub = lane >> 3, comp = lane & 7;
    int nm = g_nmulti;
    for (int j4 = gw * 4 + sub; j4 < nm; j4 += nw * 4) {
        long long r = g_multilist[j4];
        float fc = (float)g_vcount[r];
        long long o = 19LL * V + r * 32 + comp * 4;
        if (VEC == 4) {
            float4 v = *(float4*)&out[o];
            v.x = __fdiv_rn(v.x, fc);
            v.y = __fdiv_rn(v.y, fc);
            v.z = __fdiv_rn(v.z, fc);
            v.w = __fdiv_rn(v.w, fc);
            *(float4*)&out[o] = v;
        } else {
            #pragma unroll
            for (int k = 0; k < 4; k++) out[o + k] = __fdiv_rn(out[o + k], fc);
        }
    }
}

// fused: per-voxel scalar outputs + windowed-global-sort median (fast selection)
__global__ void k_final(float* __restrict__ out, const float* __restrict__ vs,
                        long long V, int N) {
    long long r = (long long)blockIdx.x * blockDim.x + threadIdx.x;
    if (r >= V) return;
    float vs1 = __ldg(&vs[1]), vs2 = __ldg(&vs[2]), vs3 = __ldg(&vs[3]);
    float mn1 = __uint_as_float(g_st.pcmin_bits[1]);
    float mn2 = __uint_as_float(g_st.pcmin_bits[2]);
    float mn3 = __uint_as_float(g_st.pcmin_bits[3]);
    int c = g_vcount[r];
    float sx = out[15LL * V + r * 4 + 0];
    float sy = out[15LL * V + r * 4 + 1];
    float sz = out[15LL * V + r * 4 + 2];
    float sw = out[15LL * V + r * 4 + 3];
    if (c > 1) {
        float fc = (float)c;
        sx = __fdiv_rn(sx, fc);
        sy = __fdiv_rn(sy, fc);
        sz = __fdiv_rn(sz, fc);
        sw = __fdiv_rn(sw, fc);
        out[15LL * V + r * 4 + 0] = sx;
        out[15LL * V + r * 4 + 1] = sy;
        out[15LL * V + r * 4 + 2] = sz;
        out[15LL * V + r * 4 + 3] = sw;
    }
    int key = g_cellof[r];
    int c0 = (key >> 24) & 255, c1 = (key >> 16) & 255, c2 = (key >> 8) & 255, c3 = key & 255;
    out[r] = (float)(int)rintf(sx);
    out[V + r * 3 + 0] = sy;
    out[V + r * 3 + 1] = sz;
    out[V + r * 3 + 2] = sw;
    float t1 = __fadd_rn(__fmul_rn((float)c1, vs1), mn1);
    float t2 = __fadd_rn(__fmul_rn((float)c2, vs2), mn2);
    float t3 = __fadd_rn(__fmul_rn((float)c3, vs3), mn3);
    float ctr1 = __fadd_rn(t1, __fdiv_rn(vs1, 2.0f));
    float ctr2 = __fadd_rn(t2, __fdiv_rn(vs2, 2.0f));
    float ctr3 = __fadd_rn(t3, __fdiv_rn(vs3, 2.0f));
    out[4LL * V + r * 3 + 0] = ctr1;
    out[4LL * V + r * 3 + 1] = ctr2;
    out[4LL * V + r * 3 + 2] = ctr3;
    out[7LL * V + r * 4 + 0] = sx;
    out[7LL * V + r * 4 + 1] = ctr1;
    out[7LL * V + r * 4 + 2] = ctr2;
    out[7LL * V + r * 4 + 3] = ctr3;
    out[11LL * V + r * 4 + 0] = (float)c0;
    out[11LL * V + r * 4 + 1] = (float)c1;
    out[11LL * V + r * 4 + 2] = (float)c2;
    out[11LL * V + r * 4 + 3] = (float)c3;

    // median: value at global-sort position voffset[r] + c/2, via windowed
    // selection with iterative min-with-multiplicity.
    float mx = g_st.hmax;
    int W = g_st.wwin;
    long long lo = r - W; if (lo < 0) lo = 0;
    long long hi = r + W; if (hi > V - 1) hi = V - 1;
    int s0 = g_voffset[lo];
    int sr = g_voffset[r];
    int s1 = (hi + 1 < V) ? g_voffset[hi + 1] : N;
    unsigned thr = fenc(__fmul_rn((float)r, mx));   // >= 0x80000000, so thr-1 safe
    int kk = c >> 1;
    for (int j = s0; j < sr; j++)
        if (__ldg(&g_keyA[j]) >= thr) kk++;
    unsigned last = thr - 1u;
    int remaining = kk + 1;
    unsigned ans = 0u;
    for (int guard = s1 - s0; guard > 0; guard--) {
        unsigned m = 0xFFFFFFFFu;
        int mult = 0;
        for (int j = s0; j < s1; j++) {
            unsigned k = __ldg(&g_keyA[j]);
            if (k > last) {
                if (k < m) { m = k; mult = 1; }
                else if (k == m) mult++;
            }
        }
        if (mult >= remaining) { ans = m; break; }
        remaining -= mult;
        last = m;
    }
    out[51LL * V + r] = __fsub_rn(fdec(ans), __fmul_rn((float)r, mx));
}

extern "C" void kernel_launch(void* const* d_in, const int* in_sizes, int n_in,
                              void* d_out, int out_size) {
    const float* bxyz = (const float*)d_in[0];
    const float* feat = (const float*)d_in[1];
    const float* hh = (const float*)d_in[2];
    const float* vs = (const float*)d_in[3];
    int N = in_sizes[0] / 4;
    long long V = ((long long)out_size - 5LL * N) / 52LL;
    float* out = (float*)d_out;

    void *p_w = 0, *p_vcount = 0;
    cudaGetSymbolAddress(&p_w, g_w);
    cudaGetSymbolAddress(&p_vcount, g_vcount);

    int NBW = (NWRD + WPB - 1) / WPB;
    int NBV = (int)((V + CPB - 1) / CPB);
    int BPT = (N + 255) / 256;
    int BS4 = ((N + 3) / 4 + 255) / 256;
    long long warps4 = ((long long)N + 3) / 4;
    int BW4 = (int)((warps4 * 32 + 255) / 256);
    int BVT = (int)((V + 255) / 256);

    cudaMemsetAsync(p_w, 0, sizeof(uint2) * NWRD);
    cudaMemsetAsync(p_vcount, 0, sizeof(int) * (size_t)V);

    k_init<<<1, 32>>>();
    k_stats<<<BS4, 256>>>((const float4*)bxyz, (const float4*)hh, hh, N);
    k_merge<<<BPT, 256>>>((const float4*)bxyz, vs, out, V, N);
    k_bits_partial<<<NBW, 256>>>();
    k_scan_bsums<<<1, 1024>>>(NBW);
    k_bits_final<<<NBW, 256>>>();
    k_count<<<BPT, 256>>>(out, V, N);
    k_vcount_partial<<<NBV, 256>>>((int)V);
    k_scan_bsums<<<1, 1024>>>(NBV);
    k_vcount_final<<<NBV, 256>>>(out, V, (int)V);
    if ((V & 3) == 0) {
        k_accum2v<4><<<BW4, 256>>>((const float4*)bxyz, (const float4*)feat, hh, out, V, N);
        k_voxfin_feat<4><<<2048, 256>>>(out, V);
    } else {
        k_accum2v<1><<<BW4, 256>>>((const float4*)bxyz, (const float4*)feat, hh, out, V, N);
        k_voxfin_feat<1><<<2048, 256>>>(out, V);
    }
    k_final<<<BVT, 256>>>(out, vs, V, N);
}